// round 7
// baseline (speedup 1.0000x reference)
#include <cuda_runtime.h>
#include <cuda_fp16.h>
#include <cstdint>
#include <cstddef>

#define BB   16
#define LQL  2048
#define LKL  2048
#define DDIM 1024

#define NS  3

// ---- GEMM1 (QK): CTA tile 256x128, BK=32, fused hi/lo 3-pass ---------------
#define QK_BM 256
#define QK_BN 128
#define QK_BK 32
#define QK_QT_B 16384                       // 256 rows * 64 B
#define QK_KT_B 8192                        // 128 rows * 64 B
#define QK_STAGE_B (2 * QK_QT_B + 2 * QK_KT_B)   // 48 KB
#define QK_SMEM (NS * QK_STAGE_B)                // 147456

// ---- GEMM2 (PV): CTA tile 256x128, BK=64 -----------------------------------
#define PV_BM 256
#define PV_BN 128
#define BKC 64
#define AST 72      // P row stride in halves (64 + 8 pad)
#define VST 136     // V row stride in halves (128 + 8 pad)
#define PV_STAGE_H (PV_BM * AST + 64 * VST)      // 27136 halves
#define PV_SMEM (NS * PV_STAGE_H * 2)            // 162816 B

// ---------------- scratch (static device globals) ---------------------------
__device__ __align__(16) __half g_Qh[(size_t)BB * LQL * DDIM];
__device__ __align__(16) __half g_Ql[(size_t)BB * LQL * DDIM];
__device__ __align__(16) __half g_Kh[(size_t)BB * LKL * DDIM];
__device__ __align__(16) __half g_Kl[(size_t)BB * LKL * DDIM];
__device__ __align__(16) __half g_V [(size_t)BB * LKL * DDIM];
__device__ __align__(16) float  g_S [(size_t)BB * LQL * LKL];
__device__ __align__(16) __half g_P [(size_t)BB * LQL * LKL];

// ---------------- PTX helpers ------------------------------------------------
__device__ __forceinline__ uint32_t s2u(const void* p) {
    return (uint32_t)__cvta_generic_to_shared(p);
}
__device__ __forceinline__ uint32_t sw64(uint32_t o) { return o ^ ((o >> 3) & 0x30); }

__device__ __forceinline__ void ldm4(uint32_t* r, uint32_t a) {
    asm volatile("ldmatrix.sync.aligned.m8n8.x4.shared.b16 {%0,%1,%2,%3},[%4];"
                 : "=r"(r[0]), "=r"(r[1]), "=r"(r[2]), "=r"(r[3]) : "r"(a));
}
__device__ __forceinline__ void ldm4t(uint32_t* r, uint32_t a) {
    asm volatile("ldmatrix.sync.aligned.m8n8.x4.trans.shared.b16 {%0,%1,%2,%3},[%4];"
                 : "=r"(r[0]), "=r"(r[1]), "=r"(r[2]), "=r"(r[3]) : "r"(a));
}
__device__ __forceinline__ void mma_f16(float* c, const uint32_t* a, uint32_t b0, uint32_t b1) {
    asm volatile("mma.sync.aligned.m16n8k16.row.col.f32.f16.f16.f32 "
                 "{%0,%1,%2,%3},{%4,%5,%6,%7},{%8,%9},{%0,%1,%2,%3};"
                 : "+f"(c[0]), "+f"(c[1]), "+f"(c[2]), "+f"(c[3])
                 : "r"(a[0]), "r"(a[1]), "r"(a[2]), "r"(a[3]), "r"(b0), "r"(b1));
}
__device__ __forceinline__ void cpa16(uint32_t s, const void* g) {
    asm volatile("cp.async.cg.shared.global [%0],[%1],16;" :: "r"(s), "l"(g));
}
__device__ __forceinline__ void cpcommit() { asm volatile("cp.async.commit_group;"); }

// ---------------- conversion kernels ----------------------------------------
__global__ void cvt_split_kernel(const float4* __restrict__ x, int which, int n4) {
    int i = blockIdx.x * blockDim.x + threadIdx.x;
    if (i >= n4) return;
    __half* hi = which ? g_Kh : g_Qh;
    __half* lo = which ? g_Kl : g_Ql;
    float4 v = x[i];
    __half h0 = __float2half_rn(v.x), h1 = __float2half_rn(v.y);
    __half h2 = __float2half_rn(v.z), h3 = __float2half_rn(v.w);
    __half l0 = __float2half_rn(v.x - __half2float(h0));
    __half l1 = __float2half_rn(v.y - __half2float(h1));
    __half l2 = __float2half_rn(v.z - __half2float(h2));
    __half l3 = __float2half_rn(v.w - __half2float(h3));
    ((__half2*)hi)[2 * i]     = __halves2half2(h0, h1);
    ((__half2*)hi)[2 * i + 1] = __halves2half2(h2, h3);
    ((__half2*)lo)[2 * i]     = __halves2half2(l0, l1);
    ((__half2*)lo)[2 * i + 1] = __halves2half2(l2, l3);
}

__global__ void cvt_v_kernel(const float4* __restrict__ x, int n4) {
    int i = blockIdx.x * blockDim.x + threadIdx.x;
    if (i >= n4) return;
    float4 v = x[i];
    ((__half2*)g_V)[2 * i]     = __halves2half2(__float2half_rn(v.x), __float2half_rn(v.y));
    ((__half2*)g_V)[2 * i + 1] = __halves2half2(__float2half_rn(v.z), __float2half_rn(v.w));
}

// ---- GEMM1: S = Q K^T, 256x128 tile, warp tile 64x64, fused 3-pass ----------
__global__ __launch_bounds__(256, 1)
void gemm_qk_kernel(const int* __restrict__ key_len) {
    int b  = blockIdx.z;
    int kl = key_len[b];
    int n0 = blockIdx.x * QK_BN;
    if (n0 >= kl) return;            // masked tile (also kl==0)
    int m0 = blockIdx.y * QK_BM;

    extern __shared__ __half sm[];
    uint32_t smb = s2u(sm);

    int tid = threadIdx.x;
    const __half* srcQh = g_Qh + ((size_t)b * LQL + m0) * DDIM;
    const __half* srcQl = g_Ql + ((size_t)b * LQL + m0) * DDIM;
    const __half* srcKh = g_Kh + ((size_t)b * LKL + n0) * DDIM;
    const __half* srcKl = g_Kl + ((size_t)b * LKL + n0) * DDIM;

    int lc = tid & 3;                            // 16B chunk within 64B row

    auto issue = [&](int t) {
        int k0 = t * QK_BK;
        uint32_t st = smb + (t % NS) * QK_STAGE_B;
        uint32_t tQh = st, tQl = st + QK_QT_B;
        uint32_t tKh = st + 2 * QK_QT_B, tKl = tKh + QK_KT_B;
        const __half* pQh = srcQh + k0 + lc * 8;
        const __half* pQl = srcQl + k0 + lc * 8;
        const __half* pKh = srcKh + k0 + lc * 8;
        const __half* pKl = srcKl + k0 + lc * 8;
#pragma unroll
        for (int i = 0; i < 4; i++) {            // Q tiles: 256 rows
            int row = (i * 256 + tid) >> 2;
            uint32_t so = sw64(row * 64 + lc * 16);
            cpa16(tQh + so, pQh + (size_t)row * DDIM);
            cpa16(tQl + so, pQl + (size_t)row * DDIM);
        }
#pragma unroll
        for (int i = 0; i < 2; i++) {            // K tiles: 128 rows
            int row = (i * 256 + tid) >> 2;
            uint32_t so = sw64(row * 64 + lc * 16);
            cpa16(tKh + so, pKh + (size_t)row * DDIM);
            cpa16(tKl + so, pKl + (size_t)row * DDIM);
        }
        cpcommit();
    };

    float acc[4][8][4];
#pragma unroll
    for (int mt = 0; mt < 4; mt++)
#pragma unroll
        for (int nt = 0; nt < 8; nt++)
#pragma unroll
            for (int j = 0; j < 4; j++) acc[mt][nt][j] = 0.0f;

    int lane = tid & 31, wid = tid >> 5;
    int wm = wid >> 1, wn = wid & 1;             // 4x2 warp grid, warp tile 64x64
    int arow = lane & 15, ac = lane >> 4;
    int g    = lane >> 3;
    int brow = (lane & 7) + ((g >> 1) << 3);
    int bc   = g & 1;

    const int KT = DDIM / QK_BK;                 // 32
    issue(0);
    issue(1);

    for (int s = 0; s < KT; s++) {
        if (s + 1 < KT) asm volatile("cp.async.wait_group 1;");
        else            asm volatile("cp.async.wait_group 0;");
        __syncthreads();
        if (s + 2 < KT) issue(s + 2);

        uint32_t st = smb + (s % NS) * QK_STAGE_B;
        uint32_t tQh = st, tQl = st + QK_QT_B;
        uint32_t tKh = st + 2 * QK_QT_B, tKl = tKh + QK_KT_B;

#pragma unroll
        for (int kk = 0; kk < 2; kk++) {
            uint32_t a[4][4], bh[8][2], bl[8][2];
#pragma unroll
            for (int nt2 = 0; nt2 < 4; nt2++) {
                uint32_t off = sw64((wn * 64 + nt2 * 16 + brow) * 64 + (kk * 2 + bc) * 16);
                uint32_t r[4];
                ldm4(r, tKh + off);
                bh[nt2 * 2][0] = r[0];     bh[nt2 * 2][1] = r[1];
                bh[nt2 * 2 + 1][0] = r[2]; bh[nt2 * 2 + 1][1] = r[3];
                ldm4(r, tKl + off);
                bl[nt2 * 2][0] = r[0];     bl[nt2 * 2][1] = r[1];
                bl[nt2 * 2 + 1][0] = r[2]; bl[nt2 * 2 + 1][1] = r[3];
            }
#pragma unroll
            for (int mt = 0; mt < 4; mt++) {
                uint32_t off = sw64((wm * 64 + mt * 16 + arow) * 64 + (kk * 2 + ac) * 16);
                ldm4(a[mt], tQh + off);
            }
#pragma unroll
            for (int mt = 0; mt < 4; mt++)
#pragma unroll
                for (int nt = 0; nt < 8; nt++)
                    mma_f16(acc[mt][nt], a[mt], bh[nt][0], bh[nt][1]);
#pragma unroll
            for (int mt = 0; mt < 4; mt++)
#pragma unroll
                for (int nt = 0; nt < 8; nt++)
                    mma_f16(acc[mt][nt], a[mt], bl[nt][0], bl[nt][1]);
#pragma unroll
            for (int mt = 0; mt < 4; mt++) {
                uint32_t off = sw64((wm * 64 + mt * 16 + arow) * 64 + (kk * 2 + ac) * 16);
                ldm4(a[mt], tQl + off);
            }
#pragma unroll
            for (int mt = 0; mt < 4; mt++)
#pragma unroll
                for (int nt = 0; nt < 8; nt++)
                    mma_f16(acc[mt][nt], a[mt], bh[nt][0], bh[nt][1]);
        }
    }

#pragma unroll
    for (int mt = 0; mt < 4; mt++) {
        int r0 = m0 + wm * 64 + mt * 16 + (lane >> 2);
#pragma unroll
        for (int nt = 0; nt < 8; nt++) {
            int c = n0 + wn * 64 + nt * 8 + (lane & 3) * 2;
            float* p0 = g_S + ((size_t)b * LQL + r0) * LKL + c;
            *(float2*)p0             = make_float2(acc[mt][nt][0], acc[mt][nt][1]);
            *(float2*)(p0 + 8 * LKL) = make_float2(acc[mt][nt][2], acc[mt][nt][3]);
        }
    }
}

// ---------------- row softmax with key_len mask ------------------------------
__global__ void softmax_kernel(const int* __restrict__ key_len) {
    int row = blockIdx.x;
    int b = row >> 11;
    int kl = key_len[b];
    __half* prow = g_P + (size_t)row * LKL;
    int tid = threadIdx.x;

    if (kl == 0) {                   // all masked -> uniform softmax
        __half2 u2 = __halves2half2(__float2half(1.0f / 2048.0f), __float2half(1.0f / 2048.0f));
        __half2* p2 = (__half2*)prow;
        for (int i = tid; i < LKL / 2; i += 256) p2[i] = u2;
        return;
    }

    const float* srow = g_S + (size_t)row * LKL;
    __shared__ float sh[LKL];
    __shared__ float red[256];

    float lmax = -3.4e38f;
    for (int k = tid; k < kl; k += 256) { float v = srow[k]; sh[k] = v; lmax = fmaxf(lmax, v); }
    red[tid] = lmax; __syncthreads();
    for (int s = 128; s > 0; s >>= 1) { if (tid < s) red[tid] = fmaxf(red[tid], red[tid + s]); __syncthreads(); }
    float m = red[0];
    __syncthreads();

    float lsum = 0.0f;
    for (int k = tid; k < kl; k += 256) { float e = __expf(sh[k] - m); sh[k] = e; lsum += e; }
    red[tid] = lsum; __syncthreads();
    for (int s = 128; s > 0; s >>= 1) { if (tid < s) red[tid] += red[tid + s]; __syncthreads(); }
    float inv = 1.0f / red[0];

    int kmax = ((kl + 63) >> 6) << 6;     // PV only reads up to ceil(kl/64)*64
    for (int k = tid; k < kmax; k += 256) {
        float p = (k < kl) ? sh[k] * inv : 0.0f;
        prow[k] = __float2half(p);
    }
}

// ---- GEMM2: O = P V, 256x128 tile, warp tile 64x64 --------------------------
__global__ __launch_bounds__(256, 1)
void gemm_pv_kernel(float* __restrict__ out, const int* __restrict__ key_len) {
    int b  = blockIdx.z;
    int kl = key_len[b];
    int n0 = blockIdx.x * PV_BN;     // over D
    int m0 = blockIdx.y * PV_BM;

    extern __shared__ __half sm[];
    int tid = threadIdx.x;

    auto issue = [&](int t) {
        int k0 = t * BKC;
        __half* as = sm + (t % NS) * PV_STAGE_H;
        __half* vs = as + PV_BM * AST;
#pragma unroll
        for (int i = 0; i < 8; i++) {          // P tile: 256 rows x 8 chunks
            int idx = i * 256 + tid;
            int row = idx >> 3, ch = idx & 7;
            cpa16(s2u(as + row * AST + ch * 8),
                  g_P + ((size_t)b * LQL + m0 + row) * LKL + k0 + ch * 8);
        }
#pragma unroll
        for (int i = 0; i < 4; i++) {          // V tile: 64 rows x 16 chunks
            int idx = i * 256 + tid;
            int vrow = idx >> 4, vch = idx & 15;
            cpa16(s2u(vs + vrow * VST + vch * 8),
                  g_V + ((size_t)b * LKL + k0 + vrow) * DDIM + n0 + vch * 8);
        }
        cpcommit();
    };

    float acc[4][8][4];
#pragma unroll
    for (int mt = 0; mt < 4; mt++)
#pragma unroll
        for (int nt = 0; nt < 8; nt++)
#pragma unroll
            for (int j = 0; j < 4; j++) acc[mt][nt][j] = 0.0f;

    int lane = tid & 31, wid = tid >> 5;
    int wm = wid >> 1, wn = wid & 1;           // 4x2 warp grid, warp tile 64x64
    int arow  = lane & 15;
    int akoff = (lane >> 4) << 3;
    int g     = lane >> 3;
    int vkrow = (lane & 7) + ((g & 1) << 3);
    int vnoff = (g >> 1) << 3;

    int KT = (kl == 0) ? (LKL / BKC) : ((kl + BKC - 1) >> 6);

    issue(0);
    if (KT > 1) issue(1);

    for (int s = 0; s < KT; s++) {
        if (s + 1 < KT) asm volatile("cp.async.wait_group 1;");
        else            asm volatile("cp.async.wait_group 0;");
        __syncthreads();
        if (s + 2 < KT) issue(s + 2);

        const __half* as = sm + (s % NS) * PV_STAGE_H;
        const __half* vs = as + PV_BM * AST;
#pragma unroll
        for (int kk = 0; kk < BKC / 16; kk++) {
            uint32_t a[4][4], bf[8][2];
#pragma unroll
            for (int mt = 0; mt < 4; mt++)
                ldm4(a[mt], s2u(as + (wm * 64 + mt * 16 + arow) * AST + kk * 16 + akoff));
#pragma unroll
            for (int nt2 = 0; nt2 < 4; nt2++) {
                uint32_t r[4];
                ldm4t(r, s2u(vs + (kk * 16 + vkrow) * VST + wn * 64 + nt2 * 16 + vnoff));
                bf[nt2 * 2][0] = r[0];     bf[nt2 * 2][1] = r[1];
                bf[nt2 * 2 + 1][0] = r[2]; bf[nt2 * 2 + 1][1] = r[3];
            }
#pragma unroll
            for (int mt = 0; mt < 4; mt++)
#pragma unroll
                for (int nt = 0; nt < 8; nt++)
                    mma_f16(acc[mt][nt], a[mt], bf[nt][0], bf[nt][1]);
        }
    }

#pragma unroll
    for (int mt = 0; mt < 4; mt++) {
        int r0 = m0 + wm * 64 + mt * 16 + (lane >> 2);
#pragma unroll
        for (int nt = 0; nt < 8; nt++) {
            int c = n0 + wn * 64 + nt * 8 + (lane & 3) * 2;
            float* p0 = out + ((size_t)b * LQL + r0) * DDIM + c;
            *(float2*)p0              = make_float2(acc[mt][nt][0], acc[mt][nt][1]);
            *(float2*)(p0 + 8 * DDIM) = make_float2(acc[mt][nt][2], acc[mt][nt][3]);
        }
    }
}

// ---------------- launch ------------------------------------------------------
extern "C" void kernel_launch(void* const* d_in, const int* in_sizes, int n_in,
                              void* d_out, int out_size) {
    const float* q  = (const float*)d_in[0];
    const float* k  = (const float*)d_in[1];
    const float* v  = (const float*)d_in[2];
    const int*   kl = (const int*)d_in[3];
    float* out = (float*)d_out;

    cudaFuncSetAttribute(gemm_qk_kernel, cudaFuncAttributeMaxDynamicSharedMemorySize, QK_SMEM);
    cudaFuncSetAttribute(gemm_pv_kernel, cudaFuncAttributeMaxDynamicSharedMemorySize, PV_SMEM);

    const int n4 = BB * LQL * DDIM / 4;
    cvt_split_kernel<<<n4 / 256, 256>>>((const float4*)q, 0, n4);
    cvt_split_kernel<<<n4 / 256, 256>>>((const float4*)k, 1, n4);
    cvt_v_kernel   <<<n4 / 256, 256>>>((const float4*)v, n4);

    gemm_qk_kernel<<<dim3(LKL / QK_BN, LQL / QK_BM, BB), 256, QK_SMEM>>>(kl);
    softmax_kernel<<<BB * LQL, 256>>>(kl);
    gemm_pv_kernel<<<dim3(DDIM / PV_BN, LQL / PV_BM, BB), 256, PV_SMEM>>>(out, kl);
}

// round 8
// speedup vs baseline: 1.6130x; 1.6130x over previous
#include <cuda_runtime.h>
#include <cuda_fp16.h>
#include <cstdint>
#include <cstddef>

#define BB   16
#define LQL  2048
#define LKL  2048
#define DDIM 1024

#define BM 128
#define BN 128
#define NS  3

// ---- QK fused-3-pass staging: BK=32 halves (64B rows), 4 tiles per stage ----
#define QK_BK 32
#define QK_TILE_B  8192                      // 128 rows * 64 B
#define QK_STAGE_B (4 * QK_TILE_B)           // Qh,Ql,Kh,Kl
#define QK_SMEM    (NS * QK_STAGE_B)         // 98304 B -> 2 CTAs/SM

// ---- PV staging ----
#define BKC 64
#define AST 72
#define VST 136
#define PV_STAGE_H (BM * AST + 64 * VST)
#define PV_SMEM (NS * PV_STAGE_H * 2)

// ---------------- scratch (static device globals) ---------------------------
__device__ __align__(16) __half g_Qh[(size_t)BB * LQL * DDIM];
__device__ __align__(16) __half g_Ql[(size_t)BB * LQL * DDIM];
__device__ __align__(16) __half g_Kh[(size_t)BB * LKL * DDIM];
__device__ __align__(16) __half g_Kl[(size_t)BB * LKL * DDIM];
__device__ __align__(16) __half g_V [(size_t)BB * LKL * DDIM];
__device__ __align__(16) float  g_S [(size_t)BB * LQL * LKL];
__device__ __align__(16) __half g_P [(size_t)BB * LQL * LKL];

// ---------------- PTX helpers ------------------------------------------------
__device__ __forceinline__ uint32_t s2u(const void* p) {
    return (uint32_t)__cvta_generic_to_shared(p);
}
__device__ __forceinline__ uint32_t sw64(uint32_t o) { return o ^ ((o >> 3) & 0x30); }

__device__ __forceinline__ void ldm4(uint32_t* r, uint32_t a) {
    asm volatile("ldmatrix.sync.aligned.m8n8.x4.shared.b16 {%0,%1,%2,%3},[%4];"
                 : "=r"(r[0]), "=r"(r[1]), "=r"(r[2]), "=r"(r[3]) : "r"(a));
}
__device__ __forceinline__ void ldm4t(uint32_t* r, uint32_t a) {
    asm volatile("ldmatrix.sync.aligned.m8n8.x4.trans.shared.b16 {%0,%1,%2,%3},[%4];"
                 : "=r"(r[0]), "=r"(r[1]), "=r"(r[2]), "=r"(r[3]) : "r"(a));
}
__device__ __forceinline__ void mma_f16(float* c, const uint32_t* a, uint32_t b0, uint32_t b1) {
    asm volatile("mma.sync.aligned.m16n8k16.row.col.f32.f16.f16.f32 "
                 "{%0,%1,%2,%3},{%4,%5,%6,%7},{%8,%9},{%0,%1,%2,%3};"
                 : "+f"(c[0]), "+f"(c[1]), "+f"(c[2]), "+f"(c[3])
                 : "r"(a[0]), "r"(a[1]), "r"(a[2]), "r"(a[3]), "r"(b0), "r"(b1));
}
__device__ __forceinline__ void cpa16(uint32_t s, const void* g) {
    asm volatile("cp.async.cg.shared.global [%0],[%1],16;" :: "r"(s), "l"(g));
}
__device__ __forceinline__ void cpcommit() { asm volatile("cp.async.commit_group;"); }

// ---------------- fused conversion: Q,K hi/lo split + V fp16 -----------------
__global__ void cvt_all_kernel(const float4* __restrict__ q,
                               const float4* __restrict__ k,
                               const float4* __restrict__ v, int n4) {
    int i = blockIdx.x * blockDim.x + threadIdx.x;
    if (i >= n4) return;
    {
        float4 x = q[i];
        __half h0 = __float2half_rn(x.x), h1 = __float2half_rn(x.y);
        __half h2 = __float2half_rn(x.z), h3 = __float2half_rn(x.w);
        ((__half2*)g_Qh)[2 * i]     = __halves2half2(h0, h1);
        ((__half2*)g_Qh)[2 * i + 1] = __halves2half2(h2, h3);
        ((__half2*)g_Ql)[2 * i]     = __halves2half2(
            __float2half_rn(x.x - __half2float(h0)), __float2half_rn(x.y - __half2float(h1)));
        ((__half2*)g_Ql)[2 * i + 1] = __halves2half2(
            __float2half_rn(x.z - __half2float(h2)), __float2half_rn(x.w - __half2float(h3)));
    }
    {
        float4 x = k[i];
        __half h0 = __float2half_rn(x.x), h1 = __float2half_rn(x.y);
        __half h2 = __float2half_rn(x.z), h3 = __float2half_rn(x.w);
        ((__half2*)g_Kh)[2 * i]     = __halves2half2(h0, h1);
        ((__half2*)g_Kh)[2 * i + 1] = __halves2half2(h2, h3);
        ((__half2*)g_Kl)[2 * i]     = __halves2half2(
            __float2half_rn(x.x - __half2float(h0)), __float2half_rn(x.y - __half2float(h1)));
        ((__half2*)g_Kl)[2 * i + 1] = __halves2half2(
            __float2half_rn(x.z - __half2float(h2)), __float2half_rn(x.w - __half2float(h3)));
    }
    {
        float4 x = v[i];
        ((__half2*)g_V)[2 * i]     = __halves2half2(__float2half_rn(x.x), __float2half_rn(x.y));
        ((__half2*)g_V)[2 * i + 1] = __halves2half2(__float2half_rn(x.z), __float2half_rn(x.w));
    }
}

// ---- GEMM1: S = Q K^T, fused hi/lo 3-pass, BK=32, 4 tiles/stage (R6) --------
__global__ __launch_bounds__(256, 2)
void gemm_qk_kernel(const int* __restrict__ key_len) {
    int b  = blockIdx.z;
    int kl = key_len[b];
    int n0 = blockIdx.x * BN;
    if (n0 >= kl) return;            // masked tile (also kl==0)
    int m0 = blockIdx.y * BM;

    extern __shared__ __half sm[];
    uint32_t smb = s2u(sm);

    int tid = threadIdx.x;
    const __half* srcQh = g_Qh + ((size_t)b * LQL + m0) * DDIM;
    const __half* srcQl = g_Ql + ((size_t)b * LQL + m0) * DDIM;
    const __half* srcKh = g_Kh + ((size_t)b * LKL + n0) * DDIM;
    const __half* srcKl = g_Kl + ((size_t)b * LKL + n0) * DDIM;

    int lrow0 = tid >> 2,  lc0 = tid & 3;
    int lrow1 = (256 + tid) >> 2;
    uint32_t sOff0 = sw64(lrow0 * 64 + lc0 * 16);
    uint32_t sOff1 = sw64(lrow1 * 64 + lc0 * 16);

    auto issue = [&](int t) {
        int k0 = t * QK_BK;
        uint32_t st = smb + (t % NS) * QK_STAGE_B;
        const __half* s0q = srcQh + k0 + lc0 * 8;
        const __half* s0l = srcQl + k0 + lc0 * 8;
        const __half* s0k = srcKh + k0 + lc0 * 8;
        const __half* s0m = srcKl + k0 + lc0 * 8;
        cpa16(st + sOff0,                 s0q + (size_t)lrow0 * DDIM);
        cpa16(st + sOff1,                 s0q + (size_t)lrow1 * DDIM);
        cpa16(st + QK_TILE_B + sOff0,     s0l + (size_t)lrow0 * DDIM);
        cpa16(st + QK_TILE_B + sOff1,     s0l + (size_t)lrow1 * DDIM);
        cpa16(st + 2 * QK_TILE_B + sOff0, s0k + (size_t)lrow0 * DDIM);
        cpa16(st + 2 * QK_TILE_B + sOff1, s0k + (size_t)lrow1 * DDIM);
        cpa16(st + 3 * QK_TILE_B + sOff0, s0m + (size_t)lrow0 * DDIM);
        cpa16(st + 3 * QK_TILE_B + sOff1, s0m + (size_t)lrow1 * DDIM);
        cpcommit();
    };

    float acc[4][4][4];
#pragma unroll
    for (int mt = 0; mt < 4; mt++)
#pragma unroll
        for (int nt = 0; nt < 4; nt++)
#pragma unroll
            for (int j = 0; j < 4; j++) acc[mt][nt][j] = 0.0f;

    int lane = tid & 31, wid = tid >> 5;
    int wm = wid >> 2, wn = wid & 3;
    int arow = lane & 15, ac = lane >> 4;
    int g    = lane >> 3;
    int brow = (lane & 7) + ((g >> 1) << 3);
    int bc   = g & 1;

    const int KT = DDIM / QK_BK;              // 32
    issue(0);
    issue(1);

    for (int s = 0; s < KT; s++) {
        if (s + 1 < KT) asm volatile("cp.async.wait_group 1;");
        else            asm volatile("cp.async.wait_group 0;");
        __syncthreads();
        if (s + 2 < KT) issue(s + 2);

        uint32_t st = smb + (s % NS) * QK_STAGE_B;
        uint32_t tQh = st, tQl = st + QK_TILE_B;
        uint32_t tKh = st + 2 * QK_TILE_B, tKl = st + 3 * QK_TILE_B;

#pragma unroll
        for (int kk = 0; kk < 2; kk++) {
            uint32_t a[4][4], bh[4][2], bl[4][2];
#pragma unroll
            for (int nt2 = 0; nt2 < 2; nt2++) {
                uint32_t off = sw64((wn * 32 + nt2 * 16 + brow) * 64 + (kk * 2 + bc) * 16);
                uint32_t r[4];
                ldm4(r, tKh + off);
                bh[nt2 * 2][0] = r[0];     bh[nt2 * 2][1] = r[1];
                bh[nt2 * 2 + 1][0] = r[2]; bh[nt2 * 2 + 1][1] = r[3];
                ldm4(r, tKl + off);
                bl[nt2 * 2][0] = r[0];     bl[nt2 * 2][1] = r[1];
                bl[nt2 * 2 + 1][0] = r[2]; bl[nt2 * 2 + 1][1] = r[3];
            }
#pragma unroll
            for (int mt = 0; mt < 4; mt++) {
                uint32_t off = sw64((wm * 64 + mt * 16 + arow) * 64 + (kk * 2 + ac) * 16);
                ldm4(a[mt], tQh + off);
            }
#pragma unroll
            for (int mt = 0; mt < 4; mt++)
#pragma unroll
                for (int nt = 0; nt < 4; nt++)
                    mma_f16(acc[mt][nt], a[mt], bh[nt][0], bh[nt][1]);
#pragma unroll
            for (int mt = 0; mt < 4; mt++)
#pragma unroll
                for (int nt = 0; nt < 4; nt++)
                    mma_f16(acc[mt][nt], a[mt], bl[nt][0], bl[nt][1]);
#pragma unroll
            for (int mt = 0; mt < 4; mt++) {
                uint32_t off = sw64((wm * 64 + mt * 16 + arow) * 64 + (kk * 2 + ac) * 16);
                ldm4(a[mt], tQl + off);
            }
#pragma unroll
            for (int mt = 0; mt < 4; mt++)
#pragma unroll
                for (int nt = 0; nt < 4; nt++)
                    mma_f16(acc[mt][nt], a[mt], bh[nt][0], bh[nt][1]);
        }
    }

#pragma unroll
    for (int mt = 0; mt < 4; mt++) {
        int r0 = m0 + wm * 64 + mt * 16 + (lane >> 2);
#pragma unroll
        for (int nt = 0; nt < 4; nt++) {
            int c = n0 + wn * 32 + nt * 8 + (lane & 3) * 2;
            float* p0 = g_S + ((size_t)b * LQL + r0) * LKL + c;
            *(float2*)p0             = make_float2(acc[mt][nt][0], acc[mt][nt][1]);
            *(float2*)(p0 + 8 * LKL) = make_float2(acc[mt][nt][2], acc[mt][nt][3]);
        }
    }
}

// ---------------- row softmax: shuffle reductions, vectorized ---------------
__global__ __launch_bounds__(256)
void softmax_kernel(const int* __restrict__ key_len) {
    int row = blockIdx.x;            // b*LQ + q
    int b = row >> 11;
    int kl = key_len[b];
    __half* prow = g_P + (size_t)row * LKL;
    int tid = threadIdx.x;
    int lane = tid & 31, wid = tid >> 5;

    if (kl == 0) {                   // all masked -> uniform softmax
        __half2 u2 = __halves2half2(__float2half(1.0f / 2048.0f), __float2half(1.0f / 2048.0f));
        __half2* p2 = (__half2*)prow;
        for (int i = tid; i < LKL / 2; i += 256) p2[i] = u2;
        return;
    }

    const float* srow = g_S + (size_t)row * LKL;
    __shared__ float sh[LKL];
    __shared__ float red[8];

    // pass 1: load (vectorized) + max
    float lmax = -3.4e38f;
    int kl4 = kl >> 2;
    const float4* s4 = (const float4*)srow;
    for (int i = tid; i < kl4; i += 256) {
        float4 v = s4[i];
        ((float4*)sh)[i] = v;
        lmax = fmaxf(fmaxf(lmax, fmaxf(v.x, v.y)), fmaxf(v.z, v.w));
    }
    for (int k = (kl4 << 2) + tid; k < kl; k += 256) {
        float v = srow[k]; sh[k] = v; lmax = fmaxf(lmax, v);
    }
#pragma unroll
    for (int o = 16; o > 0; o >>= 1)
        lmax = fmaxf(lmax, __shfl_xor_sync(0xffffffffu, lmax, o));
    if (lane == 0) red[wid] = lmax;
    __syncthreads();
    float m = fmaxf(fmaxf(fmaxf(red[0], red[1]), fmaxf(red[2], red[3])),
                    fmaxf(fmaxf(red[4], red[5]), fmaxf(red[6], red[7])));
    __syncthreads();

    // pass 2: exp + sum
    float lsum = 0.0f;
    for (int k = tid; k < kl; k += 256) {
        float e = __expf(sh[k] - m);
        sh[k] = e;
        lsum += e;
    }
#pragma unroll
    for (int o = 16; o > 0; o >>= 1)
        lsum += __shfl_xor_sync(0xffffffffu, lsum, o);
    if (lane == 0) red[wid] = lsum;
    __syncthreads();
    float inv = 1.0f / (red[0] + red[1] + red[2] + red[3] +
                        red[4] + red[5] + red[6] + red[7]);

    // pass 3: normalize + store fp16 up to ceil(kl/64)*64 (PV reads no further)
    int kmax = ((kl + 63) >> 6) << 6;
    __half2* p2 = (__half2*)prow;
    for (int i = tid; i < (kmax >> 1); i += 256) {
        int k = i << 1;
        float p0 = (k     < kl) ? sh[k]     * inv : 0.0f;
        float p1 = (k + 1 < kl) ? sh[k + 1] * inv : 0.0f;
        p2[i] = __halves2half2(__float2half(p0), __float2half(p1));
    }
}

// ---------------- GEMM2: O = P V (R6) ----------------------------------------
__global__ __launch_bounds__(256)
void gemm_pv_kernel(float* __restrict__ out, const int* __restrict__ key_len) {
    int b  = blockIdx.z;
    int kl = key_len[b];
    int n0 = blockIdx.x * BN;
    int m0 = blockIdx.y * BM;

    extern __shared__ __half sm[];
    int tid = threadIdx.x;

    auto issue = [&](int t) {
        int k0 = t * BKC;
        __half* as = sm + (t % NS) * PV_STAGE_H;
        __half* vs = as + BM * AST;
#pragma unroll
        for (int i = 0; i < 4; i++) {
            int idx = i * 256 + tid;
            int row = idx >> 3, ch = idx & 7;
            cpa16(s2u(as + row * AST + ch * 8),
                  g_P + ((size_t)b * LQL + m0 + row) * LKL + k0 + ch * 8);
            int vrow = idx >> 4, vch = idx & 15;
            cpa16(s2u(vs + vrow * VST + vch * 8),
                  g_V + ((size_t)b * LKL + k0 + vrow) * DDIM + n0 + vch * 8);
        }
        cpcommit();
    };

    float acc[4][4][4];
#pragma unroll
    for (int mt = 0; mt < 4; mt++)
#pragma unroll
        for (int nt = 0; nt < 4; nt++)
#pragma unroll
            for (int j = 0; j < 4; j++) acc[mt][nt][j] = 0.0f;

    int lane = tid & 31, wid = tid >> 5;
    int wm = wid >> 2, wn = wid & 3;
    int arow  = lane & 15;
    int akoff = (lane >> 4) << 3;
    int g     = lane >> 3;
    int vkrow = (lane & 7) + ((g & 1) << 3);
    int vnoff = (g >> 1) << 3;

    int KT = (kl == 0) ? (LKL / BKC) : ((kl + BKC - 1) >> 6);

    issue(0);
    if (KT > 1) issue(1);

    for (int s = 0; s < KT; s++) {
        if (s + 1 < KT) asm volatile("cp.async.wait_group 1;");
        else            asm volatile("cp.async.wait_group 0;");
        __syncthreads();
        if (s + 2 < KT) issue(s + 2);

        const __half* as = sm + (s % NS) * PV_STAGE_H;
        const __half* vs = as + BM * AST;
#pragma unroll
        for (int kk = 0; kk < BKC / 16; kk++) {
            uint32_t a[4][4], bf[4][2];
#pragma unroll
            for (int mt = 0; mt < 4; mt++)
                ldm4(a[mt], s2u(as + (wm * 64 + mt * 16 + arow) * AST + kk * 16 + akoff));
#pragma unroll
            for (int nt2 = 0; nt2 < 2; nt2++) {
                uint32_t r[4];
                ldm4t(r, s2u(vs + (kk * 16 + vkrow) * VST + wn * 32 + nt2 * 16 + vnoff));
                bf[nt2 * 2][0] = r[0];     bf[nt2 * 2][1] = r[1];
                bf[nt2 * 2 + 1][0] = r[2]; bf[nt2 * 2 + 1][1] = r[3];
            }
#pragma unroll
            for (int mt = 0; mt < 4; mt++)
#pragma unroll
                for (int nt = 0; nt < 4; nt++)
                    mma_f16(acc[mt][nt], a[mt], bf[nt][0], bf[nt][1]);
        }
    }

#pragma unroll
    for (int mt = 0; mt < 4; mt++) {
        int r0 = m0 + wm * 64 + mt * 16 + (lane >> 2);
#pragma unroll
        for (int nt = 0; nt < 4; nt++) {
            int c = n0 + wn * 32 + nt * 8 + (lane & 3) * 2;
            float* p0 = out + ((size_t)b * LQL + r0) * DDIM + c;
            *(float2*)p0              = make_float2(acc[mt][nt][0], acc[mt][nt][1]);
            *(float2*)(p0 + 8 * DDIM) = make_float2(acc[mt][nt][2], acc[mt][nt][3]);
        }
    }
}

// ---------------- launch ------------------------------------------------------
extern "C" void kernel_launch(void* const* d_in, const int* in_sizes, int n_in,
                              void* d_out, int out_size) {
    const float* q  = (const float*)d_in[0];
    const float* k  = (const float*)d_in[1];
    const float* v  = (const float*)d_in[2];
    const int*   kl = (const int*)d_in[3];
    float* out = (float*)d_out;

    cudaFuncSetAttribute(gemm_qk_kernel, cudaFuncAttributeMaxDynamicSharedMemorySize, QK_SMEM);
    cudaFuncSetAttribute(gemm_pv_kernel, cudaFuncAttributeMaxDynamicSharedMemorySize, PV_SMEM);

    const int n4 = BB * LQL * DDIM / 4;   // 8388608
    cvt_all_kernel<<<n4 / 256, 256>>>((const float4*)q, (const float4*)k,
                                      (const float4*)v, n4);

    gemm_qk_kernel<<<dim3(LKL / BN, LQL / BM, BB), 256, QK_SMEM>>>(kl);
    softmax_kernel<<<BB * LQL, 256>>>(kl);
    gemm_pv_kernel<<<dim3(DDIM / BN, LQL / BM, BB), 256, PV_SMEM>>>(out, kl);
}

// round 9
// speedup vs baseline: 1.6665x; 1.0331x over previous
#include <cuda_runtime.h>
#include <cuda_fp16.h>
#include <cstdint>
#include <cstddef>

#define BB   16
#define LQL  2048
#define LKL  2048
#define DDIM 1024

#define BM 128
#define BN 128
#define NS  3

// ---- QK fused-3-pass staging: BK=32 halves (64B rows), 4 tiles per stage ----
#define QK_BK 32
#define QK_TILE_B  8192                      // 128 rows * 64 B
#define QK_STAGE_B (4 * QK_TILE_B)           // Qh,Ql,Kh,Kl
#define QK_SMEM    (NS * QK_STAGE_B)         // 98304 B -> 2 CTAs/SM

// ---- PV staging ----
#define BKC 64
#define AST 72
#define VST 136
#define PV_STAGE_H (BM * AST + 64 * VST)
#define PV_SMEM (NS * PV_STAGE_H * 2)

// ---------------- scratch (static device globals) ---------------------------
__device__ __align__(16) __half g_Qh[(size_t)BB * LQL * DDIM];
__device__ __align__(16) __half g_Ql[(size_t)BB * LQL * DDIM];
__device__ __align__(16) __half g_Kh[(size_t)BB * LKL * DDIM];
__device__ __align__(16) __half g_Kl[(size_t)BB * LKL * DDIM];
__device__ __align__(16) __half g_V [(size_t)BB * LKL * DDIM];
__device__ __align__(16) float  g_S [(size_t)BB * LQL * LKL];
__device__ __align__(16) __half g_P [(size_t)BB * LQL * LKL];

// ---------------- PTX helpers ------------------------------------------------
__device__ __forceinline__ uint32_t s2u(const void* p) {
    return (uint32_t)__cvta_generic_to_shared(p);
}
__device__ __forceinline__ uint32_t sw64(uint32_t o) { return o ^ ((o >> 3) & 0x30); }

__device__ __forceinline__ void ldm4(uint32_t* r, uint32_t a) {
    asm volatile("ldmatrix.sync.aligned.m8n8.x4.shared.b16 {%0,%1,%2,%3},[%4];"
                 : "=r"(r[0]), "=r"(r[1]), "=r"(r[2]), "=r"(r[3]) : "r"(a));
}
__device__ __forceinline__ void ldm4t(uint32_t* r, uint32_t a) {
    asm volatile("ldmatrix.sync.aligned.m8n8.x4.trans.shared.b16 {%0,%1,%2,%3},[%4];"
                 : "=r"(r[0]), "=r"(r[1]), "=r"(r[2]), "=r"(r[3]) : "r"(a));
}
__device__ __forceinline__ void mma_f16(float* c, const uint32_t* a, uint32_t b0, uint32_t b1) {
    asm volatile("mma.sync.aligned.m16n8k16.row.col.f32.f16.f16.f32 "
                 "{%0,%1,%2,%3},{%4,%5,%6,%7},{%8,%9},{%0,%1,%2,%3};"
                 : "+f"(c[0]), "+f"(c[1]), "+f"(c[2]), "+f"(c[3])
                 : "r"(a[0]), "r"(a[1]), "r"(a[2]), "r"(a[3]), "r"(b0), "r"(b1));
}
__device__ __forceinline__ void cpa16(uint32_t s, const void* g) {
    asm volatile("cp.async.cg.shared.global [%0],[%1],16;" :: "r"(s), "l"(g));
}
__device__ __forceinline__ void cpcommit() { asm volatile("cp.async.commit_group;"); }

// ---------------- fused conversion: Q,K hi/lo split + V fp16 -----------------
__global__ void cvt_all_kernel(const float4* __restrict__ q,
                               const float4* __restrict__ k,
                               const float4* __restrict__ v, int n4) {
    int i = blockIdx.x * blockDim.x + threadIdx.x;
    if (i >= n4) return;
    {
        float4 x = q[i];
        __half h0 = __float2half_rn(x.x), h1 = __float2half_rn(x.y);
        __half h2 = __float2half_rn(x.z), h3 = __float2half_rn(x.w);
        ((__half2*)g_Qh)[2 * i]     = __halves2half2(h0, h1);
        ((__half2*)g_Qh)[2 * i + 1] = __halves2half2(h2, h3);
        ((__half2*)g_Ql)[2 * i]     = __halves2half2(
            __float2half_rn(x.x - __half2float(h0)), __float2half_rn(x.y - __half2float(h1)));
        ((__half2*)g_Ql)[2 * i + 1] = __halves2half2(
            __float2half_rn(x.z - __half2float(h2)), __float2half_rn(x.w - __half2float(h3)));
    }
    {
        float4 x = k[i];
        __half h0 = __float2half_rn(x.x), h1 = __float2half_rn(x.y);
        __half h2 = __float2half_rn(x.z), h3 = __float2half_rn(x.w);
        ((__half2*)g_Kh)[2 * i]     = __halves2half2(h0, h1);
        ((__half2*)g_Kh)[2 * i + 1] = __halves2half2(h2, h3);
        ((__half2*)g_Kl)[2 * i]     = __halves2half2(
            __float2half_rn(x.x - __half2float(h0)), __float2half_rn(x.y - __half2float(h1)));
        ((__half2*)g_Kl)[2 * i + 1] = __halves2half2(
            __float2half_rn(x.z - __half2float(h2)), __float2half_rn(x.w - __half2float(h3)));
    }
    {
        float4 x = v[i];
        ((__half2*)g_V)[2 * i]     = __halves2half2(__float2half_rn(x.x), __float2half_rn(x.y));
        ((__half2*)g_V)[2 * i + 1] = __halves2half2(__float2half_rn(x.z), __float2half_rn(x.w));
    }
}

// ---- GEMM1: S = Q K^T, fused hi/lo 3-pass, BK=32, frag-pipelined ------------
__global__ __launch_bounds__(256, 2)
void gemm_qk_kernel(const int* __restrict__ key_len) {
    int b  = blockIdx.z;
    int kl = key_len[b];
    int n0 = blockIdx.x * BN;
    if (n0 >= kl) return;            // masked tile (also kl==0)
    int m0 = blockIdx.y * BM;

    extern __shared__ __half sm[];
    uint32_t smb = s2u(sm);

    int tid = threadIdx.x;
    const __half* srcQh = g_Qh + ((size_t)b * LQL + m0) * DDIM;
    const __half* srcQl = g_Ql + ((size_t)b * LQL + m0) * DDIM;
    const __half* srcKh = g_Kh + ((size_t)b * LKL + n0) * DDIM;
    const __half* srcKl = g_Kl + ((size_t)b * LKL + n0) * DDIM;

    int lrow0 = tid >> 2,  lc0 = tid & 3;
    int lrow1 = (256 + tid) >> 2;
    uint32_t sOff0 = sw64(lrow0 * 64 + lc0 * 16);
    uint32_t sOff1 = sw64(lrow1 * 64 + lc0 * 16);

    auto issue = [&](int t) {
        int k0 = t * QK_BK;
        uint32_t st = smb + (t % NS) * QK_STAGE_B;
        const __half* s0q = srcQh + k0 + lc0 * 8;
        const __half* s0l = srcQl + k0 + lc0 * 8;
        const __half* s0k = srcKh + k0 + lc0 * 8;
        const __half* s0m = srcKl + k0 + lc0 * 8;
        cpa16(st + sOff0,                 s0q + (size_t)lrow0 * DDIM);
        cpa16(st + sOff1,                 s0q + (size_t)lrow1 * DDIM);
        cpa16(st + QK_TILE_B + sOff0,     s0l + (size_t)lrow0 * DDIM);
        cpa16(st + QK_TILE_B + sOff1,     s0l + (size_t)lrow1 * DDIM);
        cpa16(st + 2 * QK_TILE_B + sOff0, s0k + (size_t)lrow0 * DDIM);
        cpa16(st + 2 * QK_TILE_B + sOff1, s0k + (size_t)lrow1 * DDIM);
        cpa16(st + 3 * QK_TILE_B + sOff0, s0m + (size_t)lrow0 * DDIM);
        cpa16(st + 3 * QK_TILE_B + sOff1, s0m + (size_t)lrow1 * DDIM);
        cpcommit();
    };

    float acc[4][4][4];
#pragma unroll
    for (int mt = 0; mt < 4; mt++)
#pragma unroll
        for (int nt = 0; nt < 4; nt++)
#pragma unroll
            for (int j = 0; j < 4; j++) acc[mt][nt][j] = 0.0f;

    int lane = tid & 31, wid = tid >> 5;
    int wm = wid >> 2, wn = wid & 3;
    int arow = lane & 15, ac = lane >> 4;
    int g    = lane >> 3;
    int brow = (lane & 7) + ((g >> 1) << 3);
    int bc   = g & 1;

    const int KT = DDIM / QK_BK;              // 32
    issue(0);
    issue(1);

    for (int s = 0; s < KT; s++) {
        if (s + 1 < KT) asm volatile("cp.async.wait_group 1;");
        else            asm volatile("cp.async.wait_group 0;");
        __syncthreads();
        if (s + 2 < KT) issue(s + 2);

        uint32_t st = smb + (s % NS) * QK_STAGE_B;
        uint32_t tQh = st, tQl = st + QK_TILE_B;
        uint32_t tKh = st + 2 * QK_TILE_B, tKl = st + 3 * QK_TILE_B;

        uint32_t bh[2][4][2], bl[2][4][2];
        // B frags for kk=0 -> buffer 0
#pragma unroll
        for (int nt2 = 0; nt2 < 2; nt2++) {
            uint32_t off = sw64((wn * 32 + nt2 * 16 + brow) * 64 + bc * 16);
            uint32_t r[4];
            ldm4(r, tKh + off);
            bh[0][nt2 * 2][0] = r[0];     bh[0][nt2 * 2][1] = r[1];
            bh[0][nt2 * 2 + 1][0] = r[2]; bh[0][nt2 * 2 + 1][1] = r[3];
            ldm4(r, tKl + off);
            bl[0][nt2 * 2][0] = r[0];     bl[0][nt2 * 2][1] = r[1];
            bl[0][nt2 * 2 + 1][0] = r[2]; bl[0][nt2 * 2 + 1][1] = r[3];
        }

#pragma unroll
        for (int kk = 0; kk < 2; kk++) {
            uint32_t a[4][4];
#pragma unroll
            for (int mt = 0; mt < 4; mt++) {
                uint32_t off = sw64((wm * 64 + mt * 16 + arow) * 64 + (kk * 2 + ac) * 16);
                ldm4(a[mt], tQh + off);
            }
            if (kk == 0) {   // prefetch kk=1 B frags -> buffer 1 (overlaps mma below)
#pragma unroll
                for (int nt2 = 0; nt2 < 2; nt2++) {
                    uint32_t off = sw64((wn * 32 + nt2 * 16 + brow) * 64 + (2 + bc) * 16);
                    uint32_t r[4];
                    ldm4(r, tKh + off);
                    bh[1][nt2 * 2][0] = r[0];     bh[1][nt2 * 2][1] = r[1];
                    bh[1][nt2 * 2 + 1][0] = r[2]; bh[1][nt2 * 2 + 1][1] = r[3];
                    ldm4(r, tKl + off);
                    bl[1][nt2 * 2][0] = r[0];     bl[1][nt2 * 2][1] = r[1];
                    bl[1][nt2 * 2 + 1][0] = r[2]; bl[1][nt2 * 2 + 1][1] = r[3];
                }
            }
#pragma unroll
            for (int mt = 0; mt < 4; mt++)
#pragma unroll
                for (int nt = 0; nt < 4; nt++)
                    mma_f16(acc[mt][nt], a[mt], bh[kk][nt][0], bh[kk][nt][1]);
#pragma unroll
            for (int mt = 0; mt < 4; mt++)
#pragma unroll
                for (int nt = 0; nt < 4; nt++)
                    mma_f16(acc[mt][nt], a[mt], bl[kk][nt][0], bl[kk][nt][1]);
#pragma unroll
            for (int mt = 0; mt < 4; mt++) {
                uint32_t off = sw64((wm * 64 + mt * 16 + arow) * 64 + (kk * 2 + ac) * 16);
                ldm4(a[mt], tQl + off);
            }
#pragma unroll
            for (int mt = 0; mt < 4; mt++)
#pragma unroll
                for (int nt = 0; nt < 4; nt++)
                    mma_f16(acc[mt][nt], a[mt], bh[kk][nt][0], bh[kk][nt][1]);
        }
    }

#pragma unroll
    for (int mt = 0; mt < 4; mt++) {
        int r0 = m0 + wm * 64 + mt * 16 + (lane >> 2);
#pragma unroll
        for (int nt = 0; nt < 4; nt++) {
            int c = n0 + wn * 32 + nt * 8 + (lane & 3) * 2;
            float* p0 = g_S + ((size_t)b * LQL + r0) * LKL + c;
            *(float2*)p0             = make_float2(acc[mt][nt][0], acc[mt][nt][1]);
            *(float2*)(p0 + 8 * LKL) = make_float2(acc[mt][nt][2], acc[mt][nt][3]);
        }
    }
}

// ---------------- row softmax: register-resident, shuffle reductions --------
__global__ __launch_bounds__(256)
void softmax_kernel(const int* __restrict__ key_len) {
    int row = blockIdx.x;            // b*LQ + q
    int b = row >> 11;
    int kl = key_len[b];
    __half* prow = g_P + (size_t)row * LKL;
    int tid = threadIdx.x;
    int lane = tid & 31, wid = tid >> 5;

    if (kl == 0) {                   // all masked -> uniform softmax
        __half2 u2 = __halves2half2(__float2half(1.0f / 2048.0f), __float2half(1.0f / 2048.0f));
        __half2* p2 = (__half2*)prow;
        for (int i = tid; i < LKL / 2; i += 256) p2[i] = u2;
        return;
    }

    const float4* s4 = (const float4*)(g_S + (size_t)row * LKL);
    __shared__ float red[8];

    // pass 1: load into registers, mask beyond kl with -inf, block max
    float4 v[2];
    float lmax = -3.4e38f;
#pragma unroll
    for (int j = 0; j < 2; j++) {
        int idx = j * 256 + tid;
        v[j] = s4[idx];
        int k0 = idx << 2;
        if (k0 + 0 >= kl) v[j].x = -3.4e38f;
        if (k0 + 1 >= kl) v[j].y = -3.4e38f;
        if (k0 + 2 >= kl) v[j].z = -3.4e38f;
        if (k0 + 3 >= kl) v[j].w = -3.4e38f;
        lmax = fmaxf(fmaxf(lmax, fmaxf(v[j].x, v[j].y)), fmaxf(v[j].z, v[j].w));
    }
#pragma unroll
    for (int o = 16; o > 0; o >>= 1)
        lmax = fmaxf(lmax, __shfl_xor_sync(0xffffffffu, lmax, o));
    if (lane == 0) red[wid] = lmax;
    __syncthreads();
    float m = fmaxf(fmaxf(fmaxf(red[0], red[1]), fmaxf(red[2], red[3])),
                    fmaxf(fmaxf(red[4], red[5]), fmaxf(red[6], red[7])));
    __syncthreads();

    // pass 2: exp in registers + block sum (masked elems -> exp(-huge)=0)
    float lsum = 0.0f;
#pragma unroll
    for (int j = 0; j < 2; j++) {
        v[j].x = __expf(v[j].x - m);
        v[j].y = __expf(v[j].y - m);
        v[j].z = __expf(v[j].z - m);
        v[j].w = __expf(v[j].w - m);
        lsum += (v[j].x + v[j].y) + (v[j].z + v[j].w);
    }
#pragma unroll
    for (int o = 16; o > 0; o >>= 1)
        lsum += __shfl_xor_sync(0xffffffffu, lsum, o);
    if (lane == 0) red[wid] = lsum;
    __syncthreads();
    float inv = 1.0f / (red[0] + red[1] + red[2] + red[3] +
                        red[4] + red[5] + red[6] + red[7]);

    // pass 3: store fp16, only up to ceil(kl/64)*64 (PV reads no further)
    int kmax = ((kl + 63) >> 6) << 6;
#pragma unroll
    for (int j = 0; j < 2; j++) {
        int idx = j * 256 + tid;
        int k0 = idx << 2;
        if (k0 < kmax) {
            __half2 h0 = __halves2half2(__float2half(v[j].x * inv), __float2half(v[j].y * inv));
            __half2 h1 = __halves2half2(__float2half(v[j].z * inv), __float2half(v[j].w * inv));
            uint2 pack;
            pack.x = *(uint32_t*)&h0;
            pack.y = *(uint32_t*)&h1;
            *(uint2*)(prow + k0) = pack;
        }
    }
}

// ---------------- GEMM2: O = P V, frag-pipelined -----------------------------
__global__ __launch_bounds__(256, 2)
void gemm_pv_kernel(float* __restrict__ out, const int* __restrict__ key_len) {
    int b  = blockIdx.z;
    int kl = key_len[b];
    int n0 = blockIdx.x * BN;
    int m0 = blockIdx.y * BM;

    extern __shared__ __half sm[];
    int tid = threadIdx.x;

    auto issue = [&](int t) {
        int k0 = t * BKC;
        __half* as = sm + (t % NS) * PV_STAGE_H;
        __half* vs = as + BM * AST;
#pragma unroll
        for (int i = 0; i < 4; i++) {
            int idx = i * 256 + tid;
            int row = idx >> 3, ch = idx & 7;
            cpa16(s2u(as + row * AST + ch * 8),
                  g_P + ((size_t)b * LQL + m0 + row) * LKL + k0 + ch * 8);
            int vrow = idx >> 4, vch = idx & 15;
            cpa16(s2u(vs + vrow * VST + vch * 8),
                  g_V + ((size_t)b * LKL + k0 + vrow) * DDIM + n0 + vch * 8);
        }
        cpcommit();
    };

    float acc[4][4][4];
#pragma unroll
    for (int mt = 0; mt < 4; mt++)
#pragma unroll
        for (int nt = 0; nt < 4; nt++)
#pragma unroll
            for (int j = 0; j < 4; j++) acc[mt][nt][j] = 0.0f;

    int lane = tid & 31, wid = tid >> 5;
    int wm = wid >> 2, wn = wid & 3;
    int arow  = lane & 15;
    int akoff = (lane >> 4) << 3;
    int g     = lane >> 3;
    int vkrow = (lane & 7) + ((g & 1) << 3);
    int vnoff = (g >> 1) << 3;

    int KT = (kl == 0) ? (LKL / BKC) : ((kl + BKC - 1) >> 6);

    issue(0);
    if (KT > 1) issue(1);

    for (int s = 0; s < KT; s++) {
        if (s + 1 < KT) asm volatile("cp.async.wait_group 1;");
        else            asm volatile("cp.async.wait_group 0;");
        __syncthreads();
        if (s + 2 < KT) issue(s + 2);

        const __half* as = sm + (s % NS) * PV_STAGE_H;
        const __half* vs = as + BM * AST;

        uint32_t a[2][4][4], bf[2][4][2];
        // frags for kk=0 -> buffer 0
#pragma unroll
        for (int mt = 0; mt < 4; mt++)
            ldm4(a[0][mt], s2u(as + (wm * 64 + mt * 16 + arow) * AST + akoff));
#pragma unroll
        for (int nt2 = 0; nt2 < 2; nt2++) {
            uint32_t r[4];
            ldm4t(r, s2u(vs + vkrow * VST + wn * 32 + nt2 * 16 + vnoff));
            bf[0][nt2 * 2][0] = r[0];     bf[0][nt2 * 2][1] = r[1];
            bf[0][nt2 * 2 + 1][0] = r[2]; bf[0][nt2 * 2 + 1][1] = r[3];
        }

#pragma unroll
        for (int kk = 0; kk < BKC / 16; kk++) {
            int cur = kk & 1, nxt = cur ^ 1;
            if (kk < 3) {   // prefetch kk+1 frags (overlaps mma below)
#pragma unroll
                for (int mt = 0; mt < 4; mt++)
                    ldm4(a[nxt][mt],
                         s2u(as + (wm * 64 + mt * 16 + arow) * AST + (kk + 1) * 16 + akoff));
#pragma unroll
                for (int nt2 = 0; nt2 < 2; nt2++) {
                    uint32_t r[4];
                    ldm4t(r, s2u(vs + ((kk + 1) * 16 + vkrow) * VST + wn * 32 + nt2 * 16 + vnoff));
                    bf[nxt][nt2 * 2][0] = r[0];     bf[nxt][nt2 * 2][1] = r[1];
                    bf[nxt][nt2 * 2 + 1][0] = r[2]; bf[nxt][nt2 * 2 + 1][1] = r[3];
                }
            }
#pragma unroll
            for (int mt = 0; mt < 4; mt++)
#pragma unroll
                for (int nt = 0; nt < 4; nt++)
                    mma_f16(acc[mt][nt], a[cur][mt], bf[cur][nt][0], bf[cur][nt][1]);
        }
    }

#pragma unroll
    for (int mt = 0; mt < 4; mt++) {
        int r0 = m0 + wm * 64 + mt * 16 + (lane >> 2);
#pragma unroll
        for (int nt = 0; nt < 4; nt++) {
            int c = n0 + wn * 32 + nt * 8 + (lane & 3) * 2;
            float* p0 = out + ((size_t)b * LQL + r0) * DDIM + c;
            *(float2*)p0              = make_float2(acc[mt][nt][0], acc[mt][nt][1]);
            *(float2*)(p0 + 8 * DDIM) = make_float2(acc[mt][nt][2], acc[mt][nt][3]);
        }
    }
}

// ---------------- launch ------------------------------------------------------
extern "C" void kernel_launch(void* const* d_in, const int* in_sizes, int n_in,
                              void* d_out, int out_size) {
    const float* q  = (const float*)d_in[0];
    const float* k  = (const float*)d_in[1];
    const float* v  = (const float*)d_in[2];
    const int*   kl = (const int*)d_in[3];
    float* out = (float*)d_out;

    cudaFuncSetAttribute(gemm_qk_kernel, cudaFuncAttributeMaxDynamicSharedMemorySize, QK_SMEM);
    cudaFuncSetAttribute(gemm_pv_kernel, cudaFuncAttributeMaxDynamicSharedMemorySize, PV_SMEM);

    const int n4 = BB * LQL * DDIM / 4;   // 8388608
    cvt_all_kernel<<<n4 / 256, 256>>>((const float4*)q, (const float4*)k,
                                      (const float4*)v, n4);

    gemm_qk_kernel<<<dim3(LKL / BN, LQL / BM, BB), 256, QK_SMEM>>>(kl);
    softmax_kernel<<<BB * LQL, 256>>>(kl);
    gemm_pv_kernel<<<dim3(DDIM / BN, LQL / BM, BB), 256, PV_SMEM>>>(out, kl);
}

// round 10
// speedup vs baseline: 1.7336x; 1.0403x over previous
#include <cuda_runtime.h>
#include <cuda_fp16.h>
#include <cstdint>
#include <cstddef>

#define BB   16
#define LQL  2048
#define LKL  2048
#define DDIM 1024

#define BM 128
#define BN 128
#define NS  3

// ---- QK staging: BK=32 halves (64B rows), 4 tiles per stage ----
#define QK_BK 32
#define QK_TILE_B  8192                      // 128 rows * 64 B
#define QK_STAGE_B (4 * QK_TILE_B)           // Qh,Ql,Kh,Kl
#define QK_SMEM    (NS * QK_STAGE_B)         // 98304 B -> 2 CTAs/SM

// ---- PV staging ----
#define BKC 64
#define AST 72
#define VST 136
#define PV_STAGE_H (BM * AST + 64 * VST)
#define PV_SMEM (NS * PV_STAGE_H * 2)        // 107520 B -> 2 CTAs/SM

// ---------------- scratch (static device globals) ---------------------------
__device__ __align__(16) __half g_Qh[(size_t)BB * LQL * DDIM];
__device__ __align__(16) __half g_Ql[(size_t)BB * LQL * DDIM];
__device__ __align__(16) __half g_Kh[(size_t)BB * LKL * DDIM];
__device__ __align__(16) __half g_Kl[(size_t)BB * LKL * DDIM];
__device__ __align__(16) __half g_V [(size_t)BB * LKL * DDIM];
__device__ __align__(16) float  g_S [(size_t)BB * LQL * LKL];
__device__ __align__(16) __half g_P [(size_t)BB * LQL * LKL];

// ---------------- PTX helpers ------------------------------------------------
__device__ __forceinline__ uint32_t s2u(const void* p) {
    return (uint32_t)__cvta_generic_to_shared(p);
}
__device__ __forceinline__ uint32_t sw64(uint32_t o) { return o ^ ((o >> 3) & 0x30); }

__device__ __forceinline__ void ldm4(uint32_t* r, uint32_t a) {
    asm volatile("ldmatrix.sync.aligned.m8n8.x4.shared.b16 {%0,%1,%2,%3},[%4];"
                 : "=r"(r[0]), "=r"(r[1]), "=r"(r[2]), "=r"(r[3]) : "r"(a));
}
__device__ __forceinline__ void ldm4t(uint32_t* r, uint32_t a) {
    asm volatile("ldmatrix.sync.aligned.m8n8.x4.trans.shared.b16 {%0,%1,%2,%3},[%4];"
                 : "=r"(r[0]), "=r"(r[1]), "=r"(r[2]), "=r"(r[3]) : "r"(a));
}
__device__ __forceinline__ void mma_f16(float* c, const uint32_t* a, uint32_t b0, uint32_t b1) {
    asm volatile("mma.sync.aligned.m16n8k16.row.col.f32.f16.f16.f32 "
                 "{%0,%1,%2,%3},{%4,%5,%6,%7},{%8,%9},{%0,%1,%2,%3};"
                 : "+f"(c[0]), "+f"(c[1]), "+f"(c[2]), "+f"(c[3])
                 : "r"(a[0]), "r"(a[1]), "r"(a[2]), "r"(a[3]), "r"(b0), "r"(b1));
}
__device__ __forceinline__ void cpa16(uint32_t s, const void* g) {
    asm volatile("cp.async.cg.shared.global [%0],[%1],16;" :: "r"(s), "l"(g));
}
__device__ __forceinline__ void cpcommit() { asm volatile("cp.async.commit_group;"); }

// ---------------- fused conversion: Q,K hi/lo split + V fp16 -----------------
__global__ void cvt_all_kernel(const float4* __restrict__ q,
                               const float4* __restrict__ k,
                               const float4* __restrict__ v, int n4) {
    int i = blockIdx.x * blockDim.x + threadIdx.x;
    if (i >= n4) return;
    {
        float4 x = q[i];
        __half h0 = __float2half_rn(x.x), h1 = __float2half_rn(x.y);
        __half h2 = __float2half_rn(x.z), h3 = __float2half_rn(x.w);
        ((__half2*)g_Qh)[2 * i]     = __halves2half2(h0, h1);
        ((__half2*)g_Qh)[2 * i + 1] = __halves2half2(h2, h3);
        ((__half2*)g_Ql)[2 * i]     = __halves2half2(
            __float2half_rn(x.x - __half2float(h0)), __float2half_rn(x.y - __half2float(h1)));
        ((__half2*)g_Ql)[2 * i + 1] = __halves2half2(
            __float2half_rn(x.z - __half2float(h2)), __float2half_rn(x.w - __half2float(h3)));
    }
    {
        float4 x = k[i];
        __half h0 = __float2half_rn(x.x), h1 = __float2half_rn(x.y);
        __half h2 = __float2half_rn(x.z), h3 = __float2half_rn(x.w);
        ((__half2*)g_Kh)[2 * i]     = __halves2half2(h0, h1);
        ((__half2*)g_Kh)[2 * i + 1] = __halves2half2(h2, h3);
        ((__half2*)g_Kl)[2 * i]     = __halves2half2(
            __float2half_rn(x.x - __half2float(h0)), __float2half_rn(x.y - __half2float(h1)));
        ((__half2*)g_Kl)[2 * i + 1] = __halves2half2(
            __float2half_rn(x.z - __half2float(h2)), __float2half_rn(x.w - __half2float(h3)));
    }
    {
        float4 x = v[i];
        ((__half2*)g_V)[2 * i]     = __halves2half2(__float2half_rn(x.x), __float2half_rn(x.y));
        ((__half2*)g_V)[2 * i + 1] = __halves2half2(__float2half_rn(x.z), __float2half_rn(x.w));
    }
}

// ---- GEMM1: S = Q K^T, fused 3-pass, 4 warps, warp tile 64x64 ---------------
__global__ __launch_bounds__(128, 2)
void gemm_qk_kernel(const int* __restrict__ key_len) {
    int b  = blockIdx.z;
    int kl = key_len[b];
    int n0 = blockIdx.x * BN;
    if (n0 >= kl) return;            // masked tile (also kl==0)
    int m0 = blockIdx.y * BM;

    extern __shared__ __half sm[];
    uint32_t smb = s2u(sm);

    int tid = threadIdx.x;
    const __half* srcQh = g_Qh + ((size_t)b * LQL + m0) * DDIM;
    const __half* srcQl = g_Ql + ((size_t)b * LQL + m0) * DDIM;
    const __half* srcKh = g_Kh + ((size_t)b * LKL + n0) * DDIM;
    const __half* srcKl = g_Kl + ((size_t)b * LKL + n0) * DDIM;

    int lc = tid & 3, lr = tid >> 2;              // 32 rows per pass

    auto issue = [&](int t) {
        int k0 = t * QK_BK;
        uint32_t st = smb + (t % NS) * QK_STAGE_B;
        const __half* pQh = srcQh + k0 + lc * 8;
        const __half* pQl = srcQl + k0 + lc * 8;
        const __half* pKh = srcKh + k0 + lc * 8;
        const __half* pKl = srcKl + k0 + lc * 8;
#pragma unroll
        for (int p = 0; p < 4; p++) {
            int row = p * 32 + lr;
            uint32_t so = sw64(row * 64 + lc * 16);
            cpa16(st + so,                 pQh + (size_t)row * DDIM);
            cpa16(st + QK_TILE_B + so,     pQl + (size_t)row * DDIM);
            cpa16(st + 2 * QK_TILE_B + so, pKh + (size_t)row * DDIM);
            cpa16(st + 3 * QK_TILE_B + so, pKl + (size_t)row * DDIM);
        }
        cpcommit();
    };

    float acc[4][8][4];
#pragma unroll
    for (int mt = 0; mt < 4; mt++)
#pragma unroll
        for (int nt = 0; nt < 8; nt++)
#pragma unroll
            for (int j = 0; j < 4; j++) acc[mt][nt][j] = 0.0f;

    int lane = tid & 31, wid = tid >> 5;
    int wm = wid >> 1, wn = wid & 1;              // 2x2 grid, warp tile 64x64
    int arow = lane & 15, ac = lane >> 4;
    int g    = lane >> 3;
    int brow = (lane & 7) + ((g >> 1) << 3);
    int bc   = g & 1;

    const int KT = DDIM / QK_BK;                  // 32
    issue(0);
    issue(1);

    for (int s = 0; s < KT; s++) {
        if (s + 1 < KT) asm volatile("cp.async.wait_group 1;");
        else            asm volatile("cp.async.wait_group 0;");
        __syncthreads();
        if (s + 2 < KT) issue(s + 2);

        uint32_t st = smb + (s % NS) * QK_STAGE_B;
        uint32_t tQh = st, tQl = st + QK_TILE_B;
        uint32_t tKh = st + 2 * QK_TILE_B, tKl = st + 3 * QK_TILE_B;

#pragma unroll
        for (int kk = 0; kk < 2; kk++) {
            uint32_t a[4][4], bh[8][2], bl[8][2];
#pragma unroll
            for (int nt2 = 0; nt2 < 4; nt2++) {
                uint32_t off = sw64((wn * 64 + nt2 * 16 + brow) * 64 + (kk * 2 + bc) * 16);
                uint32_t r[4];
                ldm4(r, tKh + off);
                bh[nt2 * 2][0] = r[0];     bh[nt2 * 2][1] = r[1];
                bh[nt2 * 2 + 1][0] = r[2]; bh[nt2 * 2 + 1][1] = r[3];
                ldm4(r, tKl + off);
                bl[nt2 * 2][0] = r[0];     bl[nt2 * 2][1] = r[1];
                bl[nt2 * 2 + 1][0] = r[2]; bl[nt2 * 2 + 1][1] = r[3];
            }
#pragma unroll
            for (int mt = 0; mt < 4; mt++) {
                uint32_t off = sw64((wm * 64 + mt * 16 + arow) * 64 + (kk * 2 + ac) * 16);
                ldm4(a[mt], tQh + off);
            }
#pragma unroll
            for (int mt = 0; mt < 4; mt++)
#pragma unroll
                for (int nt = 0; nt < 8; nt++)
                    mma_f16(acc[mt][nt], a[mt], bh[nt][0], bh[nt][1]);
#pragma unroll
            for (int mt = 0; mt < 4; mt++)
#pragma unroll
                for (int nt = 0; nt < 8; nt++)
                    mma_f16(acc[mt][nt], a[mt], bl[nt][0], bl[nt][1]);
#pragma unroll
            for (int mt = 0; mt < 4; mt++) {
                uint32_t off = sw64((wm * 64 + mt * 16 + arow) * 64 + (kk * 2 + ac) * 16);
                ldm4(a[mt], tQl + off);
            }
#pragma unroll
            for (int mt = 0; mt < 4; mt++)
#pragma unroll
                for (int nt = 0; nt < 8; nt++)
                    mma_f16(acc[mt][nt], a[mt], bh[nt][0], bh[nt][1]);
        }
    }

#pragma unroll
    for (int mt = 0; mt < 4; mt++) {
        int r0 = m0 + wm * 64 + mt * 16 + (lane >> 2);
#pragma unroll
        for (int nt = 0; nt < 8; nt++) {
            int c = n0 + wn * 64 + nt * 8 + (lane & 3) * 2;
            float* p0 = g_S + ((size_t)b * LQL + r0) * LKL + c;
            *(float2*)p0             = make_float2(acc[mt][nt][0], acc[mt][nt][1]);
            *(float2*)(p0 + 8 * LKL) = make_float2(acc[mt][nt][2], acc[mt][nt][3]);
        }
    }
}

// ---------------- row softmax: register-resident, shuffle reductions --------
__global__ __launch_bounds__(256)
void softmax_kernel(const int* __restrict__ key_len) {
    int row = blockIdx.x;
    int b = row >> 11;
    int kl = key_len[b];
    __half* prow = g_P + (size_t)row * LKL;
    int tid = threadIdx.x;
    int lane = tid & 31, wid = tid >> 5;

    if (kl == 0) {                   // all masked -> uniform softmax
        __half2 u2 = __halves2half2(__float2half(1.0f / 2048.0f), __float2half(1.0f / 2048.0f));
        __half2* p2 = (__half2*)prow;
        for (int i = tid; i < LKL / 2; i += 256) p2[i] = u2;
        return;
    }

    const float4* s4 = (const float4*)(g_S + (size_t)row * LKL);
    __shared__ float red[8];

    float4 v[2];
    float lmax = -3.4e38f;
#pragma unroll
    for (int j = 0; j < 2; j++) {
        int idx = j * 256 + tid;
        v[j] = s4[idx];
        int k0 = idx << 2;
        if (k0 + 0 >= kl) v[j].x = -3.4e38f;
        if (k0 + 1 >= kl) v[j].y = -3.4e38f;
        if (k0 + 2 >= kl) v[j].z = -3.4e38f;
        if (k0 + 3 >= kl) v[j].w = -3.4e38f;
        lmax = fmaxf(fmaxf(lmax, fmaxf(v[j].x, v[j].y)), fmaxf(v[j].z, v[j].w));
    }
#pragma unroll
    for (int o = 16; o > 0; o >>= 1)
        lmax = fmaxf(lmax, __shfl_xor_sync(0xffffffffu, lmax, o));
    if (lane == 0) red[wid] = lmax;
    __syncthreads();
    float m = fmaxf(fmaxf(fmaxf(red[0], red[1]), fmaxf(red[2], red[3])),
                    fmaxf(fmaxf(red[4], red[5]), fmaxf(red[6], red[7])));
    __syncthreads();

    float lsum = 0.0f;
#pragma unroll
    for (int j = 0; j < 2; j++) {
        v[j].x = __expf(v[j].x - m);
        v[j].y = __expf(v[j].y - m);
        v[j].z = __expf(v[j].z - m);
        v[j].w = __expf(v[j].w - m);
        lsum += (v[j].x + v[j].y) + (v[j].z + v[j].w);
    }
#pragma unroll
    for (int o = 16; o > 0; o >>= 1)
        lsum += __shfl_xor_sync(0xffffffffu, lsum, o);
    if (lane == 0) red[wid] = lsum;
    __syncthreads();
    float inv = 1.0f / (red[0] + red[1] + red[2] + red[3] +
                        red[4] + red[5] + red[6] + red[7]);

    int kmax = ((kl + 63) >> 6) << 6;
#pragma unroll
    for (int j = 0; j < 2; j++) {
        int idx = j * 256 + tid;
        int k0 = idx << 2;
        if (k0 < kmax) {
            __half2 h0 = __halves2half2(__float2half(v[j].x * inv), __float2half(v[j].y * inv));
            __half2 h1 = __halves2half2(__float2half(v[j].z * inv), __float2half(v[j].w * inv));
            uint2 pack;
            pack.x = *(uint32_t*)&h0;
            pack.y = *(uint32_t*)&h1;
            *(uint2*)(prow + k0) = pack;
        }
    }
}

// ---- GEMM2: O = P V, 4 warps, warp tile 64x64 -------------------------------
__global__ __launch_bounds__(128, 2)
void gemm_pv_kernel(float* __restrict__ out, const int* __restrict__ key_len) {
    int b  = blockIdx.z;
    int kl = key_len[b];
    int n0 = blockIdx.x * BN;
    int m0 = blockIdx.y * BM;

    extern __shared__ __half sm[];
    int tid = threadIdx.x;

    auto issue = [&](int t) {
        int k0 = t * BKC;
        __half* as = sm + (t % NS) * PV_STAGE_H;
        __half* vs = as + BM * AST;
#pragma unroll
        for (int i = 0; i < 8; i++) {
            int idx = i * 128 + tid;
            int row = idx >> 3, ch = idx & 7;
            cpa16(s2u(as + row * AST + ch * 8),
                  g_P + ((size_t)b * LQL + m0 + row) * LKL + k0 + ch * 8);
            int vrow = idx >> 4, vch = idx & 15;
            cpa16(s2u(vs + vrow * VST + vch * 8),
                  g_V + ((size_t)b * LKL + k0 + vrow) * DDIM + n0 + vch * 8);
        }
        cpcommit();
    };

    float acc[4][8][4];
#pragma unroll
    for (int mt = 0; mt < 4; mt++)
#pragma unroll
        for (int nt = 0; nt < 8; nt++)
#pragma unroll
            for (int j = 0; j < 4; j++) acc[mt][nt][j] = 0.0f;

    int lane = tid & 31, wid = tid >> 5;
    int wm = wid >> 1, wn = wid & 1;              // 2x2 grid, warp tile 64x64
    int arow  = lane & 15;
    int akoff = (lane >> 4) << 3;
    int g     = lane >> 3;
    int vkrow = (lane & 7) + ((g & 1) << 3);
    int vnoff = (g >> 1) << 3;

    int KT = (kl == 0) ? (LKL / BKC) : ((kl + BKC - 1) >> 6);

    issue(0);
    if (KT > 1) issue(1);

    for (int s = 0; s < KT; s++) {
        if (s + 1 < KT) asm volatile("cp.async.wait_group 1;");
        else            asm volatile("cp.async.wait_group 0;");
        __syncthreads();
        if (s + 2 < KT) issue(s + 2);

        const __half* as = sm + (s % NS) * PV_STAGE_H;
        const __half* vs = as + BM * AST;
#pragma unroll
        for (int kk = 0; kk < BKC / 16; kk++) {
            uint32_t a[4][4], bf[8][2];
#pragma unroll
            for (int mt = 0; mt < 4; mt++)
                ldm4(a[mt], s2u(as + (wm * 64 + mt * 16 + arow) * AST + kk * 16 + akoff));
#pragma unroll
            for (int nt2 = 0; nt2 < 4; nt2++) {
                uint32_t r[4];
                ldm4t(r, s2u(vs + (kk * 16 + vkrow) * VST + wn * 64 + nt2 * 16 + vnoff));
                bf[nt2 * 2][0] = r[0];     bf[nt2 * 2][1] = r[1];
                bf[nt2 * 2 + 1][0] = r[2]; bf[nt2 * 2 + 1][1] = r[3];
            }
#pragma unroll
            for (int mt = 0; mt < 4; mt++)
#pragma unroll
                for (int nt = 0; nt < 8; nt++)
                    mma_f16(acc[mt][nt], a[mt], bf[nt][0], bf[nt][1]);
        }
    }

#pragma unroll
    for (int mt = 0; mt < 4; mt++) {
        int r0 = m0 + wm * 64 + mt * 16 + (lane >> 2);
#pragma unroll
        for (int nt = 0; nt < 8; nt++) {
            int c = n0 + wn * 64 + nt * 8 + (lane & 3) * 2;
            float* p0 = out + ((size_t)b * LQL + r0) * DDIM + c;
            *(float2*)p0              = make_float2(acc[mt][nt][0], acc[mt][nt][1]);
            *(float2*)(p0 + 8 * DDIM) = make_float2(acc[mt][nt][2], acc[mt][nt][3]);
        }
    }
}

// ---------------- launch ------------------------------------------------------
extern "C" void kernel_launch(void* const* d_in, const int* in_sizes, int n_in,
                              void* d_out, int out_size) {
    const float* q  = (const float*)d_in[0];
    const float* k  = (const float*)d_in[1];
    const float* v  = (const float*)d_in[2];
    const int*   kl = (const int*)d_in[3];
    float* out = (float*)d_out;

    cudaFuncSetAttribute(gemm_qk_kernel, cudaFuncAttributeMaxDynamicSharedMemorySize, QK_SMEM);
    cudaFuncSetAttribute(gemm_pv_kernel, cudaFuncAttributeMaxDynamicSharedMemorySize, PV_SMEM);

    const int n4 = BB * LQL * DDIM / 4;   // 8388608
    cvt_all_kernel<<<n4 / 256, 256>>>((const float4*)q, (const float4*)k,
                                      (const float4*)v, n4);

    gemm_qk_kernel<<<dim3(LKL / BN, LQL / BM, BB), 128, QK_SMEM>>>(kl);
    softmax_kernel<<<BB * LQL, 256>>>(kl);
    gemm_pv_kernel<<<dim3(DDIM / BN, LQL / BM, BB), 128, PV_SMEM>>>(out, kl);
}

// round 11
// speedup vs baseline: 1.7426x; 1.0052x over previous
#include <cuda_runtime.h>
#include <cuda_fp16.h>
#include <cstdint>
#include <cstddef>

#define BB   16
#define LQL  2048
#define LKL  2048
#define DDIM 1024

#define BM 128
#define BN 128
#define NS  3

// ---- QK staging: BK=32 halves (64B rows), 4 tiles per stage ----
#define QK_BK 32
#define QK_TILE_B  8192                      // 128 rows * 64 B
#define QK_STAGE_B (4 * QK_TILE_B)           // Qh,Ql,Kh,Kl
#define QK_SMEM    (NS * QK_STAGE_B)         // 98304 B -> 2 CTAs/SM

// ---- PV staging ----
#define BKC 64
#define AST 72
#define VST 136
#define PV_STAGE_H (BM * AST + 64 * VST)
#define PV_SMEM (NS * PV_STAGE_H * 2)        // 107520 B -> 2 CTAs/SM

// ---------------- scratch (static device globals) ---------------------------
__device__ __align__(16) __half g_Qh[(size_t)BB * LQL * DDIM];
__device__ __align__(16) __half g_Ql[(size_t)BB * LQL * DDIM];
__device__ __align__(16) __half g_Kh[(size_t)BB * LKL * DDIM];
__device__ __align__(16) __half g_Kl[(size_t)BB * LKL * DDIM];
__device__ __align__(16) __half g_V [(size_t)BB * LKL * DDIM];
__device__ __align__(16) float  g_S [(size_t)BB * LQL * LKL];
__device__ __align__(16) __half g_P [(size_t)BB * LQL * LKL];

// ---------------- PTX helpers ------------------------------------------------
__device__ __forceinline__ uint32_t s2u(const void* p) {
    return (uint32_t)__cvta_generic_to_shared(p);
}
__device__ __forceinline__ uint32_t sw64(uint32_t o) { return o ^ ((o >> 3) & 0x30); }

__device__ __forceinline__ void ldm4(uint32_t* r, uint32_t a) {
    asm volatile("ldmatrix.sync.aligned.m8n8.x4.shared.b16 {%0,%1,%2,%3},[%4];"
                 : "=r"(r[0]), "=r"(r[1]), "=r"(r[2]), "=r"(r[3]) : "r"(a));
}
__device__ __forceinline__ void ldm4t(uint32_t* r, uint32_t a) {
    asm volatile("ldmatrix.sync.aligned.m8n8.x4.trans.shared.b16 {%0,%1,%2,%3},[%4];"
                 : "=r"(r[0]), "=r"(r[1]), "=r"(r[2]), "=r"(r[3]) : "r"(a));
}
__device__ __forceinline__ void mma_f16(float* c, const uint32_t* a, uint32_t b0, uint32_t b1) {
    asm volatile("mma.sync.aligned.m16n8k16.row.col.f32.f16.f16.f32 "
                 "{%0,%1,%2,%3},{%4,%5,%6,%7},{%8,%9},{%0,%1,%2,%3};"
                 : "+f"(c[0]), "+f"(c[1]), "+f"(c[2]), "+f"(c[3])
                 : "r"(a[0]), "r"(a[1]), "r"(a[2]), "r"(a[3]), "r"(b0), "r"(b1));
}
__device__ __forceinline__ void cpa16(uint32_t s, const void* g) {
    asm volatile("cp.async.cg.shared.global [%0],[%1],16;" :: "r"(s), "l"(g));
}
__device__ __forceinline__ void cpcommit() { asm volatile("cp.async.commit_group;"); }

// ---------------- fused conversion: Q,K hi/lo split + V fp16 -----------------
__global__ void cvt_all_kernel(const float4* __restrict__ q,
                               const float4* __restrict__ k,
                               const float4* __restrict__ v, int n4) {
    int i = blockIdx.x * blockDim.x + threadIdx.x;
    if (i >= n4) return;
    {
        float4 x = q[i];
        __half h0 = __float2half_rn(x.x), h1 = __float2half_rn(x.y);
        __half h2 = __float2half_rn(x.z), h3 = __float2half_rn(x.w);
        ((__half2*)g_Qh)[2 * i]     = __halves2half2(h0, h1);
        ((__half2*)g_Qh)[2 * i + 1] = __halves2half2(h2, h3);
        ((__half2*)g_Ql)[2 * i]     = __halves2half2(
            __float2half_rn(x.x - __half2float(h0)), __float2half_rn(x.y - __half2float(h1)));
        ((__half2*)g_Ql)[2 * i + 1] = __halves2half2(
            __float2half_rn(x.z - __half2float(h2)), __float2half_rn(x.w - __half2float(h3)));
    }
    {
        float4 x = k[i];
        __half h0 = __float2half_rn(x.x), h1 = __float2half_rn(x.y);
        __half h2 = __float2half_rn(x.z), h3 = __float2half_rn(x.w);
        ((__half2*)g_Kh)[2 * i]     = __halves2half2(h0, h1);
        ((__half2*)g_Kh)[2 * i + 1] = __halves2half2(h2, h3);
        ((__half2*)g_Kl)[2 * i]     = __halves2half2(
            __float2half_rn(x.x - __half2float(h0)), __float2half_rn(x.y - __half2float(h1)));
        ((__half2*)g_Kl)[2 * i + 1] = __halves2half2(
            __float2half_rn(x.z - __half2float(h2)), __float2half_rn(x.w - __half2float(h3)));
    }
    {
        float4 x = v[i];
        ((__half2*)g_V)[2 * i]     = __halves2half2(__float2half_rn(x.x), __float2half_rn(x.y));
        ((__half2*)g_V)[2 * i + 1] = __halves2half2(__float2half_rn(x.z), __float2half_rn(x.w));
    }
}

// ---- GEMM1: S = Q K^T, fused 3-pass, 4 warps, warp tile 64x64 ---------------
__global__ __launch_bounds__(128, 2)
void gemm_qk_kernel(const int* __restrict__ key_len) {
    int b  = blockIdx.z;
    int kl = key_len[b];
    int n0 = blockIdx.x * BN;
    if (n0 >= kl) return;            // masked tile (also kl==0)
    int m0 = blockIdx.y * BM;

    extern __shared__ __half sm[];
    uint32_t smb = s2u(sm);

    int tid = threadIdx.x;
    const __half* srcQh = g_Qh + ((size_t)b * LQL + m0) * DDIM;
    const __half* srcQl = g_Ql + ((size_t)b * LQL + m0) * DDIM;
    const __half* srcKh = g_Kh + ((size_t)b * LKL + n0) * DDIM;
    const __half* srcKl = g_Kl + ((size_t)b * LKL + n0) * DDIM;

    int lc = tid & 3, lr = tid >> 2;              // 32 rows per pass

    auto issue = [&](int t) {
        int k0 = t * QK_BK;
        uint32_t st = smb + (t % NS) * QK_STAGE_B;
        const __half* pQh = srcQh + k0 + lc * 8;
        const __half* pQl = srcQl + k0 + lc * 8;
        const __half* pKh = srcKh + k0 + lc * 8;
        const __half* pKl = srcKl + k0 + lc * 8;
#pragma unroll
        for (int p = 0; p < 4; p++) {
            int row = p * 32 + lr;
            uint32_t so = sw64(row * 64 + lc * 16);
            cpa16(st + so,                 pQh + (size_t)row * DDIM);
            cpa16(st + QK_TILE_B + so,     pQl + (size_t)row * DDIM);
            cpa16(st + 2 * QK_TILE_B + so, pKh + (size_t)row * DDIM);
            cpa16(st + 3 * QK_TILE_B + so, pKl + (size_t)row * DDIM);
        }
        cpcommit();
    };

    float acc[4][8][4];
#pragma unroll
    for (int mt = 0; mt < 4; mt++)
#pragma unroll
        for (int nt = 0; nt < 8; nt++)
#pragma unroll
            for (int j = 0; j < 4; j++) acc[mt][nt][j] = 0.0f;

    int lane = tid & 31, wid = tid >> 5;
    int wm = wid >> 1, wn = wid & 1;              // 2x2 grid, warp tile 64x64
    int arow = lane & 15, ac = lane >> 4;
    int g    = lane >> 3;
    int brow = (lane & 7) + ((g >> 1) << 3);
    int bc   = g & 1;

    const int KT = DDIM / QK_BK;                  // 32
    issue(0);
    issue(1);

    for (int s = 0; s < KT; s++) {
        if (s + 1 < KT) asm volatile("cp.async.wait_group 1;");
        else            asm volatile("cp.async.wait_group 0;");
        __syncthreads();
        if (s + 2 < KT) issue(s + 2);

        uint32_t st = smb + (s % NS) * QK_STAGE_B;
        uint32_t tQh = st, tQl = st + QK_TILE_B;
        uint32_t tKh = st + 2 * QK_TILE_B, tKl = st + 3 * QK_TILE_B;

#pragma unroll
        for (int kk = 0; kk < 2; kk++) {
            uint32_t aQh[4][4], aQl[4][4], bh[8][2], bl[8][2];
#pragma unroll
            for (int nt2 = 0; nt2 < 4; nt2++) {
                uint32_t off = sw64((wn * 64 + nt2 * 16 + brow) * 64 + (kk * 2 + bc) * 16);
                uint32_t r[4];
                ldm4(r, tKh + off);
                bh[nt2 * 2][0] = r[0];     bh[nt2 * 2][1] = r[1];
                bh[nt2 * 2 + 1][0] = r[2]; bh[nt2 * 2 + 1][1] = r[3];
                ldm4(r, tKl + off);
                bl[nt2 * 2][0] = r[0];     bl[nt2 * 2][1] = r[1];
                bl[nt2 * 2 + 1][0] = r[2]; bl[nt2 * 2 + 1][1] = r[3];
            }
#pragma unroll
            for (int mt = 0; mt < 4; mt++) {
                uint32_t off = sw64((wm * 64 + mt * 16 + arow) * 64 + (kk * 2 + ac) * 16);
                ldm4(aQh[mt], tQh + off);
            }
            // prefetch Ql frags now; their latency hides under the two trains below
#pragma unroll
            for (int mt = 0; mt < 4; mt++) {
                uint32_t off = sw64((wm * 64 + mt * 16 + arow) * 64 + (kk * 2 + ac) * 16);
                ldm4(aQl[mt], tQl + off);
            }
#pragma unroll
            for (int mt = 0; mt < 4; mt++)
#pragma unroll
                for (int nt = 0; nt < 8; nt++)
                    mma_f16(acc[mt][nt], aQh[mt], bh[nt][0], bh[nt][1]);
#pragma unroll
            for (int mt = 0; mt < 4; mt++)
#pragma unroll
                for (int nt = 0; nt < 8; nt++)
                    mma_f16(acc[mt][nt], aQh[mt], bl[nt][0], bl[nt][1]);
#pragma unroll
            for (int mt = 0; mt < 4; mt++)
#pragma unroll
                for (int nt = 0; nt < 8; nt++)
                    mma_f16(acc[mt][nt], aQl[mt], bh[nt][0], bh[nt][1]);
        }
    }

#pragma unroll
    for (int mt = 0; mt < 4; mt++) {
        int r0 = m0 + wm * 64 + mt * 16 + (lane >> 2);
#pragma unroll
        for (int nt = 0; nt < 8; nt++) {
            int c = n0 + wn * 64 + nt * 8 + (lane & 3) * 2;
            float* p0 = g_S + ((size_t)b * LQL + r0) * LKL + c;
            *(float2*)p0             = make_float2(acc[mt][nt][0], acc[mt][nt][1]);
            *(float2*)(p0 + 8 * LKL) = make_float2(acc[mt][nt][2], acc[mt][nt][3]);
        }
    }
}

// ---------------- row softmax: masked loads, register-resident ---------------
__global__ __launch_bounds__(256)
void softmax_kernel(const int* __restrict__ key_len) {
    int row = blockIdx.x;
    int b = row >> 11;
    int kl = key_len[b];
    __half* prow = g_P + (size_t)row * LKL;
    int tid = threadIdx.x;
    int lane = tid & 31, wid = tid >> 5;

    if (kl == 0) {                   // all masked -> uniform softmax
        __half2 u2 = __halves2half2(__float2half(1.0f / 2048.0f), __float2half(1.0f / 2048.0f));
        __half2* p2 = (__half2*)prow;
        for (int i = tid; i < LKL / 2; i += 256) p2[i] = u2;
        return;
    }

    const float4* s4 = (const float4*)(g_S + (size_t)row * LKL);
    __shared__ float red[8];

    // pass 1: masked load (skip columns >= kl entirely), block max
    float4 v[2];
    float lmax = -3.4e38f;
#pragma unroll
    for (int j = 0; j < 2; j++) {
        int idx = j * 256 + tid;
        int k0 = idx << 2;
        if (k0 < kl) {
            v[j] = s4[idx];
            if (k0 + 1 >= kl) v[j].y = -3.4e38f;
            if (k0 + 2 >= kl) v[j].z = -3.4e38f;
            if (k0 + 3 >= kl) v[j].w = -3.4e38f;
            lmax = fmaxf(fmaxf(lmax, fmaxf(v[j].x, v[j].y)), fmaxf(v[j].z, v[j].w));
        } else {
            v[j] = make_float4(-3.4e38f, -3.4e38f, -3.4e38f, -3.4e38f);
        }
    }
#pragma unroll
    for (int o = 16; o > 0; o >>= 1)
        lmax = fmaxf(lmax, __shfl_xor_sync(0xffffffffu, lmax, o));
    if (lane == 0) red[wid] = lmax;
    __syncthreads();
    float m = fmaxf(fmaxf(fmaxf(red[0], red[1]), fmaxf(red[2], red[3])),
                    fmaxf(fmaxf(red[4], red[5]), fmaxf(red[6], red[7])));
    __syncthreads();

    // pass 2: exp + block sum (masked elems -> 0)
    float lsum = 0.0f;
#pragma unroll
    for (int j = 0; j < 2; j++) {
        v[j].x = __expf(v[j].x - m);
        v[j].y = __expf(v[j].y - m);
        v[j].z = __expf(v[j].z - m);
        v[j].w = __expf(v[j].w - m);
        lsum += (v[j].x + v[j].y) + (v[j].z + v[j].w);
    }
#pragma unroll
    for (int o = 16; o > 0; o >>= 1)
        lsum += __shfl_xor_sync(0xffffffffu, lsum, o);
    if (lane == 0) red[wid] = lsum;
    __syncthreads();
    float inv = 1.0f / (red[0] + red[1] + red[2] + red[3] +
                        red[4] + red[5] + red[6] + red[7]);

    // pass 3: store fp16 up to ceil(kl/64)*64 (PV reads no further)
    int kmax = ((kl + 63) >> 6) << 6;
#pragma unroll
    for (int j = 0; j < 2; j++) {
        int idx = j * 256 + tid;
        int k0 = idx << 2;
        if (k0 < kmax) {
            __half2 h0 = __halves2half2(__float2half(v[j].x * inv), __float2half(v[j].y * inv));
            __half2 h1 = __halves2half2(__float2half(v[j].z * inv), __float2half(v[j].w * inv));
            uint2 pack;
            pack.x = *(uint32_t*)&h0;
            pack.y = *(uint32_t*)&h1;
            *(uint2*)(prow + k0) = pack;
        }
    }
}

// ---- GEMM2: O = P V, 4 warps, warp tile 64x64 (R10 config) ------------------
__global__ __launch_bounds__(128, 2)
void gemm_pv_kernel(float* __restrict__ out, const int* __restrict__ key_len) {
    int b  = blockIdx.z;
    int kl = key_len[b];
    int n0 = blockIdx.x * BN;
    int m0 = blockIdx.y * BM;

    extern __shared__ __half sm[];
    int tid = threadIdx.x;

    auto issue = [&](int t) {
        int k0 = t * BKC;
        __half* as = sm + (t % NS) * PV_STAGE_H;
        __half* vs = as + BM * AST;
#pragma unroll
        for (int i = 0; i < 8; i++) {
            int idx = i * 128 + tid;
            int row = idx >> 3, ch = idx & 7;
            cpa16(s2u(as + row * AST + ch * 8),
                  g_P + ((size_t)b * LQL + m0 + row) * LKL + k0 + ch * 8);
            int vrow = idx >> 4, vch = idx & 15;
            cpa16(s2u(vs + vrow * VST + vch * 8),
                  g_V + ((size_t)b * LKL + k0 + vrow) * DDIM + n0 + vch * 8);
        }
        cpcommit();
    };

    float acc[4][8][4];
#pragma unroll
    for (int mt = 0; mt < 4; mt++)
#pragma unroll
        for (int nt = 0; nt < 8; nt++)
#pragma unroll
            for (int j = 0; j < 4; j++) acc[mt][nt][j] = 0.0f;

    int lane = tid & 31, wid = tid >> 5;
    int wm = wid >> 1, wn = wid & 1;              // 2x2 grid, warp tile 64x64
    int arow  = lane & 15;
    int akoff = (lane >> 4) << 3;
    int g     = lane >> 3;
    int vkrow = (lane & 7) + ((g & 1) << 3);
    int vnoff = (g >> 1) << 3;

    int KT = (kl == 0) ? (LKL / BKC) : ((kl + BKC - 1) >> 6);

    issue(0);
    if (KT > 1) issue(1);

    for (int s = 0; s < KT; s++) {
        if (s + 1 < KT) asm volatile("cp.async.wait_group 1;");
        else            asm volatile("cp.async.wait_group 0;");
        __syncthreads();
        if (s + 2 < KT) issue(s + 2);

        const __half* as = sm + (s % NS) * PV_STAGE_H;
        const __half* vs = as + BM * AST;
#pragma unroll
        for (int kk = 0; kk < BKC / 16; kk++) {
            uint32_t a[4][4], bf[8][2];
#pragma unroll
            for (int mt = 0; mt < 4; mt++)
                ldm4(a[mt], s2u(as + (wm * 64 + mt * 16 + arow) * AST + kk * 16 + akoff));
#pragma unroll
            for (int nt2 = 0; nt2 < 4; nt2++) {
                uint32_t r[4];
                ldm4t(r, s2u(vs + (kk * 16 + vkrow) * VST + wn * 64 + nt2 * 16 + vnoff));
                bf[nt2 * 2][0] = r[0];     bf[nt2 * 2][1] = r[1];
                bf[nt2 * 2 + 1][0] = r[2]; bf[nt2 * 2 + 1][1] = r[3];
            }
#pragma unroll
            for (int mt = 0; mt < 4; mt++)
#pragma unroll
                for (int nt = 0; nt < 8; nt++)
                    mma_f16(acc[mt][nt], a[mt], bf[nt][0], bf[nt][1]);
        }
    }

#pragma unroll
    for (int mt = 0; mt < 4; mt++) {
        int r0 = m0 + wm * 64 + mt * 16 + (lane >> 2);
#pragma unroll
        for (int nt = 0; nt < 8; nt++) {
            int c = n0 + wn * 64 + nt * 8 + (lane & 3) * 2;
            float* p0 = out + ((size_t)b * LQL + r0) * DDIM + c;
            *(float2*)p0              = make_float2(acc[mt][nt][0], acc[mt][nt][1]);
            *(float2*)(p0 + 8 * DDIM) = make_float2(acc[mt][nt][2], acc[mt][nt][3]);
        }
    }
}

// ---------------- launch ------------------------------------------------------
extern "C" void kernel_launch(void* const* d_in, const int* in_sizes, int n_in,
                              void* d_out, int out_size) {
    const float* q  = (const float*)d_in[0];
    const float* k  = (const float*)d_in[1];
    const float* v  = (const float*)d_in[2];
    const int*   kl = (const int*)d_in[3];
    float* out = (float*)d_out;

    cudaFuncSetAttribute(gemm_qk_kernel, cudaFuncAttributeMaxDynamicSharedMemorySize, QK_SMEM);
    cudaFuncSetAttribute(gemm_pv_kernel, cudaFuncAttributeMaxDynamicSharedMemorySize, PV_SMEM);

    const int n4 = BB * LQL * DDIM / 4;   // 8388608
    cvt_all_kernel<<<n4 / 256, 256>>>((const float4*)q, (const float4*)k,
                                      (const float4*)v, n4);

    gemm_qk_kernel<<<dim3(LKL / BN, LQL / BM, BB), 128, QK_SMEM>>>(kl);
    softmax_kernel<<<BB * LQL, 256>>>(kl);
    gemm_pv_kernel<<<dim3(DDIM / BN, LQL / BM, BB), 128, PV_SMEM>>>(out, kl);
}

// round 12
// speedup vs baseline: 1.8091x; 1.0382x over previous
#include <cuda_runtime.h>
#include <cuda_fp16.h>
#include <cstdint>
#include <cstddef>

#define BB   16
#define LQL  2048
#define LKL  2048
#define DDIM 1024

#define BM 128
#define BN 128
#define NS  3

// ---- QK staging: BK=32 halves (64B rows), 4 tiles per stage ----
#define QK_BK 32
#define QK_TILE_B  8192                      // 128 rows * 64 B
#define QK_STAGE_B (4 * QK_TILE_B)           // Qh,Ql,Kh,Kl
#define QK_SMEM    (NS * QK_STAGE_B)         // 98304 B -> 2 CTAs/SM

// ---- PV staging: BK=32, 2 tiles (P, Vt) per stage ----
#define PV_BK 32
#define PV_TILE_B 8192
#define PV_STAGE_B (2 * PV_TILE_B)           // 16 KB
#define PV_SMEM (NS * PV_STAGE_B)            // 49152 B -> 2 CTAs/SM

// ---------------- scratch (static device globals) ---------------------------
__device__ __align__(16) __half g_Qh[(size_t)BB * LQL * DDIM];
__device__ __align__(16) __half g_Ql[(size_t)BB * LQL * DDIM];
__device__ __align__(16) __half g_Kh[(size_t)BB * LKL * DDIM];
__device__ __align__(16) __half g_Kl[(size_t)BB * LKL * DDIM];
__device__ __align__(16) __half g_Vt[(size_t)BB * DDIM * LKL];  // V^T: [b][d][k]
__device__ __align__(16) float  g_S [(size_t)BB * LQL * LKL];
__device__ __align__(16) __half g_P [(size_t)BB * LQL * LKL];

// ---------------- PTX helpers ------------------------------------------------
__device__ __forceinline__ uint32_t s2u(const void* p) {
    return (uint32_t)__cvta_generic_to_shared(p);
}
__device__ __forceinline__ uint32_t sw64(uint32_t o) { return o ^ ((o >> 3) & 0x30); }

__device__ __forceinline__ void ldm4(uint32_t* r, uint32_t a) {
    asm volatile("ldmatrix.sync.aligned.m8n8.x4.shared.b16 {%0,%1,%2,%3},[%4];"
                 : "=r"(r[0]), "=r"(r[1]), "=r"(r[2]), "=r"(r[3]) : "r"(a));
}
__device__ __forceinline__ void mma_f16(float* c, const uint32_t* a, uint32_t b0, uint32_t b1) {
    asm volatile("mma.sync.aligned.m16n8k16.row.col.f32.f16.f16.f32 "
                 "{%0,%1,%2,%3},{%4,%5,%6,%7},{%8,%9},{%0,%1,%2,%3};"
                 : "+f"(c[0]), "+f"(c[1]), "+f"(c[2]), "+f"(c[3])
                 : "r"(a[0]), "r"(a[1]), "r"(a[2]), "r"(a[3]), "r"(b0), "r"(b1));
}
__device__ __forceinline__ void cpa16(uint32_t s, const void* g) {
    asm volatile("cp.async.cg.shared.global [%0],[%1],16;" :: "r"(s), "l"(g));
}
__device__ __forceinline__ void cpcommit() { asm volatile("cp.async.commit_group;"); }

// ---------------- conversion: Q,K hi/lo split --------------------------------
__global__ void cvt_qk_kernel(const float4* __restrict__ q,
                              const float4* __restrict__ k, int n4) {
    int i = blockIdx.x * blockDim.x + threadIdx.x;
    if (i >= n4) return;
    {
        float4 x = q[i];
        __half h0 = __float2half_rn(x.x), h1 = __float2half_rn(x.y);
        __half h2 = __float2half_rn(x.z), h3 = __float2half_rn(x.w);
        ((__half2*)g_Qh)[2 * i]     = __halves2half2(h0, h1);
        ((__half2*)g_Qh)[2 * i + 1] = __halves2half2(h2, h3);
        ((__half2*)g_Ql)[2 * i]     = __halves2half2(
            __float2half_rn(x.x - __half2float(h0)), __float2half_rn(x.y - __half2float(h1)));
        ((__half2*)g_Ql)[2 * i + 1] = __halves2half2(
            __float2half_rn(x.z - __half2float(h2)), __float2half_rn(x.w - __half2float(h3)));
    }
    {
        float4 x = k[i];
        __half h0 = __float2half_rn(x.x), h1 = __float2half_rn(x.y);
        __half h2 = __float2half_rn(x.z), h3 = __float2half_rn(x.w);
        ((__half2*)g_Kh)[2 * i]     = __halves2half2(h0, h1);
        ((__half2*)g_Kh)[2 * i + 1] = __halves2half2(h2, h3);
        ((__half2*)g_Kl)[2 * i]     = __halves2half2(
            __float2half_rn(x.x - __half2float(h0)), __float2half_rn(x.y - __half2float(h1)));
        ((__half2*)g_Kl)[2 * i + 1] = __halves2half2(
            __float2half_rn(x.z - __half2float(h2)), __float2half_rn(x.w - __half2float(h3)));
    }
}

// V [b][k][d] fp32 -> g_Vt [b][d][k] fp16 (tiled transpose via smem)
__global__ void cvt_v_t_kernel(const float* __restrict__ v) {
    __shared__ __half tile[32][33];
    int b  = blockIdx.z;
    int k0 = blockIdx.y * 32;
    int d0 = blockIdx.x * 32;
    int x = threadIdx.x, y = threadIdx.y;
    const float* src = v + ((size_t)b * LKL + k0) * DDIM + d0;
#pragma unroll
    for (int i = 0; i < 4; i++)
        tile[y + 8 * i][x] = __float2half_rn(src[(size_t)(y + 8 * i) * DDIM + x]);
    __syncthreads();
    __half* dst = g_Vt + ((size_t)b * DDIM + d0) * LKL + k0;
#pragma unroll
    for (int i = 0; i < 4; i++)
        dst[(size_t)(y + 8 * i) * LKL + x] = tile[x][y + 8 * i];
}

// ---- GEMM1: S = Q K^T, fused 3-pass, 4 warps, warp tile 64x64 ---------------
__global__ __launch_bounds__(128, 2)
void gemm_qk_kernel(const int* __restrict__ key_len) {
    int b  = blockIdx.z;
    int kl = key_len[b];
    int n0 = blockIdx.x * BN;
    if (n0 >= kl) return;            // masked tile (also kl==0)
    int m0 = blockIdx.y * BM;

    extern __shared__ __half sm[];
    uint32_t smb = s2u(sm);

    int tid = threadIdx.x;
    const __half* srcQh = g_Qh + ((size_t)b * LQL + m0) * DDIM;
    const __half* srcQl = g_Ql + ((size_t)b * LQL + m0) * DDIM;
    const __half* srcKh = g_Kh + ((size_t)b * LKL + n0) * DDIM;
    const __half* srcKl = g_Kl + ((size_t)b * LKL + n0) * DDIM;

    int lc = tid & 3, lr = tid >> 2;

    auto issue = [&](int t) {
        int k0 = t * QK_BK;
        uint32_t st = smb + (t % NS) * QK_STAGE_B;
        const __half* pQh = srcQh + k0 + lc * 8;
        const __half* pQl = srcQl + k0 + lc * 8;
        const __half* pKh = srcKh + k0 + lc * 8;
        const __half* pKl = srcKl + k0 + lc * 8;
#pragma unroll
        for (int p = 0; p < 4; p++) {
            int row = p * 32 + lr;
            uint32_t so = sw64(row * 64 + lc * 16);
            cpa16(st + so,                 pQh + (size_t)row * DDIM);
            cpa16(st + QK_TILE_B + so,     pQl + (size_t)row * DDIM);
            cpa16(st + 2 * QK_TILE_B + so, pKh + (size_t)row * DDIM);
            cpa16(st + 3 * QK_TILE_B + so, pKl + (size_t)row * DDIM);
        }
        cpcommit();
    };

    float acc[4][8][4];
#pragma unroll
    for (int mt = 0; mt < 4; mt++)
#pragma unroll
        for (int nt = 0; nt < 8; nt++)
#pragma unroll
            for (int j = 0; j < 4; j++) acc[mt][nt][j] = 0.0f;

    int lane = tid & 31, wid = tid >> 5;
    int wm = wid >> 1, wn = wid & 1;              // 2x2 grid, warp tile 64x64
    int arow = lane & 15, ac = lane >> 4;
    int g    = lane >> 3;
    int brow = (lane & 7) + ((g >> 1) << 3);
    int bc   = g & 1;

    const int KT = DDIM / QK_BK;                  // 32
    issue(0);
    issue(1);

    for (int s = 0; s < KT; s++) {
        if (s + 1 < KT) asm volatile("cp.async.wait_group 1;");
        else            asm volatile("cp.async.wait_group 0;");
        __syncthreads();
        if (s + 2 < KT) issue(s + 2);

        uint32_t st = smb + (s % NS) * QK_STAGE_B;
        uint32_t tQh = st, tQl = st + QK_TILE_B;
        uint32_t tKh = st + 2 * QK_TILE_B, tKl = st + 3 * QK_TILE_B;

#pragma unroll
        for (int kk = 0; kk < 2; kk++) {
            uint32_t aQh[4][4], aQl[4][4], bh[8][2], bl[8][2];
#pragma unroll
            for (int nt2 = 0; nt2 < 4; nt2++) {
                uint32_t off = sw64((wn * 64 + nt2 * 16 + brow) * 64 + (kk * 2 + bc) * 16);
                uint32_t r[4];
                ldm4(r, tKh + off);
                bh[nt2 * 2][0] = r[0];     bh[nt2 * 2][1] = r[1];
                bh[nt2 * 2 + 1][0] = r[2]; bh[nt2 * 2 + 1][1] = r[3];
                ldm4(r, tKl + off);
                bl[nt2 * 2][0] = r[0];     bl[nt2 * 2][1] = r[1];
                bl[nt2 * 2 + 1][0] = r[2]; bl[nt2 * 2 + 1][1] = r[3];
            }
#pragma unroll
            for (int mt = 0; mt < 4; mt++) {
                uint32_t off = sw64((wm * 64 + mt * 16 + arow) * 64 + (kk * 2 + ac) * 16);
                ldm4(aQh[mt], tQh + off);
            }
#pragma unroll
            for (int mt = 0; mt < 4; mt++) {
                uint32_t off = sw64((wm * 64 + mt * 16 + arow) * 64 + (kk * 2 + ac) * 16);
                ldm4(aQl[mt], tQl + off);
            }
#pragma unroll
            for (int mt = 0; mt < 4; mt++)
#pragma unroll
                for (int nt = 0; nt < 8; nt++)
                    mma_f16(acc[mt][nt], aQh[mt], bh[nt][0], bh[nt][1]);
#pragma unroll
            for (int mt = 0; mt < 4; mt++)
#pragma unroll
                for (int nt = 0; nt < 8; nt++)
                    mma_f16(acc[mt][nt], aQh[mt], bl[nt][0], bl[nt][1]);
#pragma unroll
            for (int mt = 0; mt < 4; mt++)
#pragma unroll
                for (int nt = 0; nt < 8; nt++)
                    mma_f16(acc[mt][nt], aQl[mt], bh[nt][0], bh[nt][1]);
        }
    }

#pragma unroll
    for (int mt = 0; mt < 4; mt++) {
        int r0 = m0 + wm * 64 + mt * 16 + (lane >> 2);
#pragma unroll
        for (int nt = 0; nt < 8; nt++) {
            int c = n0 + wn * 64 + nt * 8 + (lane & 3) * 2;
            float* p0 = g_S + ((size_t)b * LQL + r0) * LKL + c;
            *(float2*)p0             = make_float2(acc[mt][nt][0], acc[mt][nt][1]);
            *(float2*)(p0 + 8 * LKL) = make_float2(acc[mt][nt][2], acc[mt][nt][3]);
        }
    }
}

// ---------------- row softmax: masked loads, register-resident ---------------
__global__ __launch_bounds__(256)
void softmax_kernel(const int* __restrict__ key_len) {
    int row = blockIdx.x;
    int b = row >> 11;
    int kl = key_len[b];
    __half* prow = g_P + (size_t)row * LKL;
    int tid = threadIdx.x;
    int lane = tid & 31, wid = tid >> 5;

    if (kl == 0) {                   // all masked -> uniform softmax
        __half2 u2 = __halves2half2(__float2half(1.0f / 2048.0f), __float2half(1.0f / 2048.0f));
        __half2* p2 = (__half2*)prow;
        for (int i = tid; i < LKL / 2; i += 256) p2[i] = u2;
        return;
    }

    const float4* s4 = (const float4*)(g_S + (size_t)row * LKL);
    __shared__ float red[8];

    float4 v[2];
    float lmax = -3.4e38f;
#pragma unroll
    for (int j = 0; j < 2; j++) {
        int idx = j * 256 + tid;
        int k0 = idx << 2;
        if (k0 < kl) {
            v[j] = s4[idx];
            if (k0 + 1 >= kl) v[j].y = -3.4e38f;
            if (k0 + 2 >= kl) v[j].z = -3.4e38f;
            if (k0 + 3 >= kl) v[j].w = -3.4e38f;
            lmax = fmaxf(fmaxf(lmax, fmaxf(v[j].x, v[j].y)), fmaxf(v[j].z, v[j].w));
        } else {
            v[j] = make_float4(-3.4e38f, -3.4e38f, -3.4e38f, -3.4e38f);
        }
    }
#pragma unroll
    for (int o = 16; o > 0; o >>= 1)
        lmax = fmaxf(lmax, __shfl_xor_sync(0xffffffffu, lmax, o));
    if (lane == 0) red[wid] = lmax;
    __syncthreads();
    float m = fmaxf(fmaxf(fmaxf(red[0], red[1]), fmaxf(red[2], red[3])),
                    fmaxf(fmaxf(red[4], red[5]), fmaxf(red[6], red[7])));
    __syncthreads();

    float lsum = 0.0f;
#pragma unroll
    for (int j = 0; j < 2; j++) {
        v[j].x = __expf(v[j].x - m);
        v[j].y = __expf(v[j].y - m);
        v[j].z = __expf(v[j].z - m);
        v[j].w = __expf(v[j].w - m);
        lsum += (v[j].x + v[j].y) + (v[j].z + v[j].w);
    }
#pragma unroll
    for (int o = 16; o > 0; o >>= 1)
        lsum += __shfl_xor_sync(0xffffffffu, lsum, o);
    if (lane == 0) red[wid] = lsum;
    __syncthreads();
    float inv = 1.0f / (red[0] + red[1] + red[2] + red[3] +
                        red[4] + red[5] + red[6] + red[7]);

    int kmax = ((kl + 63) >> 6) << 6;
#pragma unroll
    for (int j = 0; j < 2; j++) {
        int idx = j * 256 + tid;
        int k0 = idx << 2;
        if (k0 < kmax) {
            __half2 h0 = __halves2half2(__float2half(v[j].x * inv), __float2half(v[j].y * inv));
            __half2 h1 = __halves2half2(__float2half(v[j].z * inv), __float2half(v[j].w * inv));
            uint2 pack;
            pack.x = *(uint32_t*)&h0;
            pack.y = *(uint32_t*)&h1;
            *(uint2*)(prow + k0) = pack;
        }
    }
}

// ---- GEMM2: O = P V  (QK-clone: BK=32, both operands normal ldm4) -----------
__global__ __launch_bounds__(128, 2)
void gemm_pv_kernel(float* __restrict__ out, const int* __restrict__ key_len) {
    int b  = blockIdx.z;
    int kl = key_len[b];
    int n0 = blockIdx.x * BN;        // over D
    int m0 = blockIdx.y * BM;

    extern __shared__ __half sm[];
    uint32_t smb = s2u(sm);
    int tid = threadIdx.x;

    const __half* srcP  = g_P  + ((size_t)b * LQL + m0) * LKL;
    const __half* srcVt = g_Vt + ((size_t)b * DDIM + n0) * LKL;

    int lc = tid & 3, lr = tid >> 2;

    auto issue = [&](int t) {
        int k0 = t * PV_BK;
        uint32_t st = smb + (t % NS) * PV_STAGE_B;
        const __half* pP = srcP  + k0 + lc * 8;
        const __half* pV = srcVt + k0 + lc * 8;
#pragma unroll
        for (int p = 0; p < 4; p++) {
            int row = p * 32 + lr;
            uint32_t so = sw64(row * 64 + lc * 16);
            cpa16(st + so,             pP + (size_t)row * LKL);
            cpa16(st + PV_TILE_B + so, pV + (size_t)row * LKL);
        }
        cpcommit();
    };

    float acc[4][8][4];
#pragma unroll
    for (int mt = 0; mt < 4; mt++)
#pragma unroll
        for (int nt = 0; nt < 8; nt++)
#pragma unroll
            for (int j = 0; j < 4; j++) acc[mt][nt][j] = 0.0f;

    int lane = tid & 31, wid = tid >> 5;
    int wm = wid >> 1, wn = wid & 1;              // 2x2 grid, warp tile 64x64
    int arow = lane & 15, ac = lane >> 4;
    int g    = lane >> 3;
    int brow = (lane & 7) + ((g >> 1) << 3);
    int bc   = g & 1;

    int KT = (kl == 0) ? (LKL / PV_BK) : ((kl + PV_BK - 1) >> 5);

    issue(0);
    if (KT > 1) issue(1);

    for (int s = 0; s < KT; s++) {
        if (s + 1 < KT) asm volatile("cp.async.wait_group 1;");
        else            asm volatile("cp.async.wait_group 0;");
        __syncthreads();
        if (s + 2 < KT) issue(s + 2);

        uint32_t st = smb + (s % NS) * PV_STAGE_B;
        uint32_t tP = st, tV = st + PV_TILE_B;

#pragma unroll
        for (int kk = 0; kk < 2; kk++) {
            uint32_t a[4][4], bf[8][2];
#pragma unroll
            for (int nt2 = 0; nt2 < 4; nt2++) {
                uint32_t off = sw64((wn * 64 + nt2 * 16 + brow) * 64 + (kk * 2 + bc) * 16);
                uint32_t r[4];
                ldm4(r, tV + off);
                bf[nt2 * 2][0] = r[0];     bf[nt2 * 2][1] = r[1];
                bf[nt2 * 2 + 1][0] = r[2]; bf[nt2 * 2 + 1][1] = r[3];
            }
#pragma unroll
            for (int mt = 0; mt < 4; mt++) {
                uint32_t off = sw64((wm * 64 + mt * 16 + arow) * 64 + (kk * 2 + ac) * 16);
                ldm4(a[mt], tP + off);
            }
#pragma unroll
            for (int mt = 0; mt < 4; mt++)
#pragma unroll
                for (int nt = 0; nt < 8; nt++)
                    mma_f16(acc[mt][nt], a[mt], bf[nt][0], bf[nt][1]);
        }
    }

#pragma unroll
    for (int mt = 0; mt < 4; mt++) {
        int r0 = m0 + wm * 64 + mt * 16 + (lane >> 2);
#pragma unroll
        for (int nt = 0; nt < 8; nt++) {
            int c = n0 + wn * 64 + nt * 8 + (lane & 3) * 2;
            float* p0 = out + ((size_t)b * LQL + r0) * DDIM + c;
            *(float2*)p0              = make_float2(acc[mt][nt][0], acc[mt][nt][1]);
            *(float2*)(p0 + 8 * DDIM) = make_float2(acc[mt][nt][2], acc[mt][nt][3]);
        }
    }
}

// ---------------- launch ------------------------------------------------------
extern "C" void kernel_launch(void* const* d_in, const int* in_sizes, int n_in,
                              void* d_out, int out_size) {
    const float* q  = (const float*)d_in[0];
    const float* k  = (const float*)d_in[1];
    const float* v  = (const float*)d_in[2];
    const int*   kl = (const int*)d_in[3];
    float* out = (float*)d_out;

    cudaFuncSetAttribute(gemm_qk_kernel, cudaFuncAttributeMaxDynamicSharedMemorySize, QK_SMEM);
    cudaFuncSetAttribute(gemm_pv_kernel, cudaFuncAttributeMaxDynamicSharedMemorySize, PV_SMEM);

    const int n4 = BB * LQL * DDIM / 4;   // 8388608
    cvt_qk_kernel<<<n4 / 256, 256>>>((const float4*)q, (const float4*)k, n4);
    cvt_v_t_kernel<<<dim3(DDIM / 32, LKL / 32, BB), dim3(32, 8)>>>(v);

    gemm_qk_kernel<<<dim3(LKL / BN, LQL / BM, BB), 128, QK_SMEM>>>(kl);
    softmax_kernel<<<BB * LQL, 256>>>(kl);
    gemm_pv_kernel<<<dim3(DDIM / BN, LQL / BM, BB), 128, PV_SMEM>>>(out, kl);
}

// round 13
// speedup vs baseline: 1.8342x; 1.0139x over previous
#include <cuda_runtime.h>
#include <cuda_fp16.h>
#include <cstdint>
#include <cstddef>

#define BB   16
#define LQL  2048
#define LKL  2048
#define DDIM 1024

#define BM 128
#define BN 128
#define NS  3

// ---- QK staging: BK=32 halves (64B rows), 4 tiles per stage ----
#define QK_BK 32
#define QK_TILE_B  8192                      // 128 rows * 64 B
#define QK_STAGE_B (4 * QK_TILE_B)           // Qh,Ql,Kh,Kl
#define QK_SMEM    (NS * QK_STAGE_B)         // 98304 B -> 2 CTAs/SM

// ---- PV staging: BK=32, 2 tiles (P, Vt) per stage, 4 stages ----
#define PV_NS 4
#define PV_BK 32
#define PV_TILE_B 8192
#define PV_STAGE_B (2 * PV_TILE_B)           // 16 KB
#define PV_SMEM (PV_NS * PV_STAGE_B)         // 65536 B -> 2 CTAs/SM

// ---------------- scratch (static device globals) ---------------------------
__device__ __align__(16) __half g_Qh[(size_t)BB * LQL * DDIM];
__device__ __align__(16) __half g_Ql[(size_t)BB * LQL * DDIM];
__device__ __align__(16) __half g_Kh[(size_t)BB * LKL * DDIM];
__device__ __align__(16) __half g_Kl[(size_t)BB * LKL * DDIM];
__device__ __align__(16) __half g_Vt[(size_t)BB * DDIM * LKL];  // V^T: [b][d][k]
__device__ __align__(16) float  g_S [(size_t)BB * LQL * LKL];
__device__ __align__(16) __half g_P [(size_t)BB * LQL * LKL];

// ---------------- PTX helpers ------------------------------------------------
__device__ __forceinline__ uint32_t s2u(const void* p) {
    return (uint32_t)__cvta_generic_to_shared(p);
}
__device__ __forceinline__ uint32_t sw64(uint32_t o) { return o ^ ((o >> 3) & 0x30); }

__device__ __forceinline__ void ldm4(uint32_t* r, uint32_t a) {
    asm volatile("ldmatrix.sync.aligned.m8n8.x4.shared.b16 {%0,%1,%2,%3},[%4];"
                 : "=r"(r[0]), "=r"(r[1]), "=r"(r[2]), "=r"(r[3]) : "r"(a));
}
__device__ __forceinline__ void mma_f16(float* c, const uint32_t* a, uint32_t b0, uint32_t b1) {
    asm volatile("mma.sync.aligned.m16n8k16.row.col.f32.f16.f16.f32 "
                 "{%0,%1,%2,%3},{%4,%5,%6,%7},{%8,%9},{%0,%1,%2,%3};"
                 : "+f"(c[0]), "+f"(c[1]), "+f"(c[2]), "+f"(c[3])
                 : "r"(a[0]), "r"(a[1]), "r"(a[2]), "r"(a[3]), "r"(b0), "r"(b1));
}
__device__ __forceinline__ void cpa16(uint32_t s, const void* g) {
    asm volatile("cp.async.cg.shared.global [%0],[%1],16;" :: "r"(s), "l"(g));
}
__device__ __forceinline__ void cpcommit() { asm volatile("cp.async.commit_group;"); }

// ---------------- conversion: Q,K hi/lo split --------------------------------
__global__ void cvt_qk_kernel(const float4* __restrict__ q,
                              const float4* __restrict__ k, int n4) {
    int i = blockIdx.x * blockDim.x + threadIdx.x;
    if (i >= n4) return;
    {
        float4 x = q[i];
        __half h0 = __float2half_rn(x.x), h1 = __float2half_rn(x.y);
        __half h2 = __float2half_rn(x.z), h3 = __float2half_rn(x.w);
        ((__half2*)g_Qh)[2 * i]     = __halves2half2(h0, h1);
        ((__half2*)g_Qh)[2 * i + 1] = __halves2half2(h2, h3);
        ((__half2*)g_Ql)[2 * i]     = __halves2half2(
            __float2half_rn(x.x - __half2float(h0)), __float2half_rn(x.y - __half2float(h1)));
        ((__half2*)g_Ql)[2 * i + 1] = __halves2half2(
            __float2half_rn(x.z - __half2float(h2)), __float2half_rn(x.w - __half2float(h3)));
    }
    {
        float4 x = k[i];
        __half h0 = __float2half_rn(x.x), h1 = __float2half_rn(x.y);
        __half h2 = __float2half_rn(x.z), h3 = __float2half_rn(x.w);
        ((__half2*)g_Kh)[2 * i]     = __halves2half2(h0, h1);
        ((__half2*)g_Kh)[2 * i + 1] = __halves2half2(h2, h3);
        ((__half2*)g_Kl)[2 * i]     = __halves2half2(
            __float2half_rn(x.x - __half2float(h0)), __float2half_rn(x.y - __half2float(h1)));
        ((__half2*)g_Kl)[2 * i + 1] = __halves2half2(
            __float2half_rn(x.z - __half2float(h2)), __float2half_rn(x.w - __half2float(h3)));
    }
}

// V [b][k][d] fp32 -> g_Vt [b][d][k] fp16; 64(k) x 32(d) tiles, half2 stores
__global__ void cvt_v_t_kernel(const float* __restrict__ v) {
    __shared__ __half tile[64][33];              // [k][d], pad
    int b  = blockIdx.z;
    int k0 = blockIdx.y * 64;
    int d0 = blockIdx.x * 32;
    int x = threadIdx.x, y = threadIdx.y;        // 32 x 8
    const float* src = v + ((size_t)b * LKL + k0) * DDIM + d0;
#pragma unroll
    for (int i = 0; i < 8; i++)                  // 64 k-rows
        tile[y + 8 * i][x] = __float2half_rn(src[(size_t)(y + 8 * i) * DDIM + x]);
    __syncthreads();
    __half* dst = g_Vt + ((size_t)b * DDIM + d0) * LKL + k0;
#pragma unroll
    for (int i = 0; i < 4; i++) {                // 32 d-rows, 64 k each as half2
        int d = y + 8 * i;
        __half2 hv = __halves2half2(tile[2 * x][d], tile[2 * x + 1][d]);
        *(__half2*)(dst + (size_t)d * LKL + 2 * x) = hv;
    }
}

// ---- GEMM1: S = Q K^T, fused 3-pass, 4 warps, warp tile 64x64 ---------------
__global__ __launch_bounds__(128, 2)
void gemm_qk_kernel(const int* __restrict__ key_len) {
    int b  = blockIdx.z;
    int kl = key_len[b];
    int n0 = blockIdx.x * BN;
    if (n0 >= kl) return;            // masked tile (also kl==0)
    int m0 = blockIdx.y * BM;

    extern __shared__ __half sm[];
    uint32_t smb = s2u(sm);

    int tid = threadIdx.x;
    const __half* srcQh = g_Qh + ((size_t)b * LQL + m0) * DDIM;
    const __half* srcQl = g_Ql + ((size_t)b * LQL + m0) * DDIM;
    const __half* srcKh = g_Kh + ((size_t)b * LKL + n0) * DDIM;
    const __half* srcKl = g_Kl + ((size_t)b * LKL + n0) * DDIM;

    int lc = tid & 3, lr = tid >> 2;

    auto issue = [&](int t) {
        int k0 = t * QK_BK;
        uint32_t st = smb + (t % NS) * QK_STAGE_B;
        const __half* pQh = srcQh + k0 + lc * 8;
        const __half* pQl = srcQl + k0 + lc * 8;
        const __half* pKh = srcKh + k0 + lc * 8;
        const __half* pKl = srcKl + k0 + lc * 8;
#pragma unroll
        for (int p = 0; p < 4; p++) {
            int row = p * 32 + lr;
            uint32_t so = sw64(row * 64 + lc * 16);
            cpa16(st + so,                 pQh + (size_t)row * DDIM);
            cpa16(st + QK_TILE_B + so,     pQl + (size_t)row * DDIM);
            cpa16(st + 2 * QK_TILE_B + so, pKh + (size_t)row * DDIM);
            cpa16(st + 3 * QK_TILE_B + so, pKl + (size_t)row * DDIM);
        }
        cpcommit();
    };

    float acc[4][8][4];
#pragma unroll
    for (int mt = 0; mt < 4; mt++)
#pragma unroll
        for (int nt = 0; nt < 8; nt++)
#pragma unroll
            for (int j = 0; j < 4; j++) acc[mt][nt][j] = 0.0f;

    int lane = tid & 31, wid = tid >> 5;
    int wm = wid >> 1, wn = wid & 1;              // 2x2 grid, warp tile 64x64
    int arow = lane & 15, ac = lane >> 4;
    int g    = lane >> 3;
    int brow = (lane & 7) + ((g >> 1) << 3);
    int bc   = g & 1;

    const int KT = DDIM / QK_BK;                  // 32
    issue(0);
    issue(1);

    for (int s = 0; s < KT; s++) {
        if (s + 1 < KT) asm volatile("cp.async.wait_group 1;");
        else            asm volatile("cp.async.wait_group 0;");
        __syncthreads();
        if (s + 2 < KT) issue(s + 2);

        uint32_t st = smb + (s % NS) * QK_STAGE_B;
        uint32_t tQh = st, tQl = st + QK_TILE_B;
        uint32_t tKh = st + 2 * QK_TILE_B, tKl = st + 3 * QK_TILE_B;

#pragma unroll
        for (int kk = 0; kk < 2; kk++) {
            uint32_t aQh[4][4], aQl[4][4], bh[8][2], bl[8][2];
#pragma unroll
            for (int nt2 = 0; nt2 < 4; nt2++) {
                uint32_t off = sw64((wn * 64 + nt2 * 16 + brow) * 64 + (kk * 2 + bc) * 16);
                uint32_t r[4];
                ldm4(r, tKh + off);
                bh[nt2 * 2][0] = r[0];     bh[nt2 * 2][1] = r[1];
                bh[nt2 * 2 + 1][0] = r[2]; bh[nt2 * 2 + 1][1] = r[3];
                ldm4(r, tKl + off);
                bl[nt2 * 2][0] = r[0];     bl[nt2 * 2][1] = r[1];
                bl[nt2 * 2 + 1][0] = r[2]; bl[nt2 * 2 + 1][1] = r[3];
            }
#pragma unroll
            for (int mt = 0; mt < 4; mt++) {
                uint32_t off = sw64((wm * 64 + mt * 16 + arow) * 64 + (kk * 2 + ac) * 16);
                ldm4(aQh[mt], tQh + off);
            }
#pragma unroll
            for (int mt = 0; mt < 4; mt++) {
                uint32_t off = sw64((wm * 64 + mt * 16 + arow) * 64 + (kk * 2 + ac) * 16);
                ldm4(aQl[mt], tQl + off);
            }
#pragma unroll
            for (int mt = 0; mt < 4; mt++)
#pragma unroll
                for (int nt = 0; nt < 8; nt++)
                    mma_f16(acc[mt][nt], aQh[mt], bh[nt][0], bh[nt][1]);
#pragma unroll
            for (int mt = 0; mt < 4; mt++)
#pragma unroll
                for (int nt = 0; nt < 8; nt++)
                    mma_f16(acc[mt][nt], aQh[mt], bl[nt][0], bl[nt][1]);
#pragma unroll
            for (int mt = 0; mt < 4; mt++)
#pragma unroll
                for (int nt = 0; nt < 8; nt++)
                    mma_f16(acc[mt][nt], aQl[mt], bh[nt][0], bh[nt][1]);
        }
    }

#pragma unroll
    for (int mt = 0; mt < 4; mt++) {
        int r0 = m0 + wm * 64 + mt * 16 + (lane >> 2);
#pragma unroll
        for (int nt = 0; nt < 8; nt++) {
            int c = n0 + wn * 64 + nt * 8 + (lane & 3) * 2;
            float* p0 = g_S + ((size_t)b * LQL + r0) * LKL + c;
            *(float2*)p0             = make_float2(acc[mt][nt][0], acc[mt][nt][1]);
            *(float2*)(p0 + 8 * LKL) = make_float2(acc[mt][nt][2], acc[mt][nt][3]);
        }
    }
}

// ---------------- row softmax: masked loads, register-resident ---------------
__global__ __launch_bounds__(256)
void softmax_kernel(const int* __restrict__ key_len) {
    int row = blockIdx.x;
    int b = row >> 11;
    int kl = key_len[b];
    __half* prow = g_P + (size_t)row * LKL;
    int tid = threadIdx.x;
    int lane = tid & 31, wid = tid >> 5;

    if (kl == 0) {                   // all masked -> uniform softmax
        __half2 u2 = __halves2half2(__float2half(1.0f / 2048.0f), __float2half(1.0f / 2048.0f));
        __half2* p2 = (__half2*)prow;
        for (int i = tid; i < LKL / 2; i += 256) p2[i] = u2;
        return;
    }

    const float4* s4 = (const float4*)(g_S + (size_t)row * LKL);
    __shared__ float red[8];

    float4 v[2];
    float lmax = -3.4e38f;
#pragma unroll
    for (int j = 0; j < 2; j++) {
        int idx = j * 256 + tid;
        int k0 = idx << 2;
        if (k0 < kl) {
            v[j] = s4[idx];
            if (k0 + 1 >= kl) v[j].y = -3.4e38f;
            if (k0 + 2 >= kl) v[j].z = -3.4e38f;
            if (k0 + 3 >= kl) v[j].w = -3.4e38f;
            lmax = fmaxf(fmaxf(lmax, fmaxf(v[j].x, v[j].y)), fmaxf(v[j].z, v[j].w));
        } else {
            v[j] = make_float4(-3.4e38f, -3.4e38f, -3.4e38f, -3.4e38f);
        }
    }
#pragma unroll
    for (int o = 16; o > 0; o >>= 1)
        lmax = fmaxf(lmax, __shfl_xor_sync(0xffffffffu, lmax, o));
    if (lane == 0) red[wid] = lmax;
    __syncthreads();
    float m = fmaxf(fmaxf(fmaxf(red[0], red[1]), fmaxf(red[2], red[3])),
                    fmaxf(fmaxf(red[4], red[5]), fmaxf(red[6], red[7])));
    __syncthreads();

    float lsum = 0.0f;
#pragma unroll
    for (int j = 0; j < 2; j++) {
        v[j].x = __expf(v[j].x - m);
        v[j].y = __expf(v[j].y - m);
        v[j].z = __expf(v[j].z - m);
        v[j].w = __expf(v[j].w - m);
        lsum += (v[j].x + v[j].y) + (v[j].z + v[j].w);
    }
#pragma unroll
    for (int o = 16; o > 0; o >>= 1)
        lsum += __shfl_xor_sync(0xffffffffu, lsum, o);
    if (lane == 0) red[wid] = lsum;
    __syncthreads();
    float inv = 1.0f / (red[0] + red[1] + red[2] + red[3] +
                        red[4] + red[5] + red[6] + red[7]);

    int kmax = ((kl + 63) >> 6) << 6;
#pragma unroll
    for (int j = 0; j < 2; j++) {
        int idx = j * 256 + tid;
        int k0 = idx << 2;
        if (k0 < kmax) {
            __half2 h0 = __halves2half2(__float2half(v[j].x * inv), __float2half(v[j].y * inv));
            __half2 h1 = __halves2half2(__float2half(v[j].z * inv), __float2half(v[j].w * inv));
            uint2 pack;
            pack.x = *(uint32_t*)&h0;
            pack.y = *(uint32_t*)&h1;
            *(uint2*)(prow + k0) = pack;
        }
    }
}

// ---- GEMM2: O = P V  (BK=32, normal ldm4 both operands, NS=4) ---------------
__global__ __launch_bounds__(128, 2)
void gemm_pv_kernel(float* __restrict__ out, const int* __restrict__ key_len) {
    int b  = blockIdx.z;
    int kl = key_len[b];
    int n0 = blockIdx.x * BN;        // over D
    int m0 = blockIdx.y * BM;

    extern __shared__ __half sm[];
    uint32_t smb = s2u(sm);
    int tid = threadIdx.x;

    const __half* srcP  = g_P  + ((size_t)b * LQL + m0) * LKL;
    const __half* srcVt = g_Vt + ((size_t)b * DDIM + n0) * LKL;

    int lc = tid & 3, lr = tid >> 2;

    auto issue = [&](int t) {
        int k0 = t * PV_BK;
        uint32_t st = smb + (t % PV_NS) * PV_STAGE_B;
        const __half* pP = srcP  + k0 + lc * 8;
        const __half* pV = srcVt + k0 + lc * 8;
#pragma unroll
        for (int p = 0; p < 4; p++) {
            int row = p * 32 + lr;
            uint32_t so = sw64(row * 64 + lc * 16);
            cpa16(st + so,             pP + (size_t)row * LKL);
            cpa16(st + PV_TILE_B + so, pV + (size_t)row * LKL);
        }
        cpcommit();
    };

    float acc[4][8][4];
#pragma unroll
    for (int mt = 0; mt < 4; mt++)
#pragma unroll
        for (int nt = 0; nt < 8; nt++)
#pragma unroll
            for (int j = 0; j < 4; j++) acc[mt][nt][j] = 0.0f;

    int lane = tid & 31, wid = tid >> 5;
    int wm = wid >> 1, wn = wid & 1;              // 2x2 grid, warp tile 64x64
    int arow = lane & 15, ac = lane >> 4;
    int g    = lane >> 3;
    int brow = (lane & 7) + ((g >> 1) << 3);
    int bc   = g & 1;

    int KT = (kl == 0) ? (LKL / PV_BK) : ((kl + PV_BK - 1) >> 5);

    issue(0);
    if (KT > 1) issue(1);
    if (KT > 2) issue(2);

    for (int s = 0; s < KT; s++) {
        if (s + 1 < KT) {
            if (s + 2 < KT) asm volatile("cp.async.wait_group 2;");
            else            asm volatile("cp.async.wait_group 1;");
        } else              asm volatile("cp.async.wait_group 0;");
        __syncthreads();
        if (s + 3 < KT) issue(s + 3);

        uint32_t st = smb + (s % PV_NS) * PV_STAGE_B;
        uint32_t tP = st, tV = st + PV_TILE_B;

#pragma unroll
        for (int kk = 0; kk < 2; kk++) {
            uint32_t a[4][4], bf[8][2];
#pragma unroll
            for (int nt2 = 0; nt2 < 4; nt2++) {
                uint32_t off = sw64((wn * 64 + nt2 * 16 + brow) * 64 + (kk * 2 + bc) * 16);
                uint32_t r[4];
                ldm4(r, tV + off);
                bf[nt2 * 2][0] = r[0];     bf[nt2 * 2][1] = r[1];
                bf[nt2 * 2 + 1][0] = r[2]; bf[nt2 * 2 + 1][1] = r[3];
            }
#pragma unroll
            for (int mt = 0; mt < 4; mt++) {
                uint32_t off = sw64((wm * 64 + mt * 16 + arow) * 64 + (kk * 2 + ac) * 16);
                ldm4(a[mt], tP + off);
            }
#pragma unroll
            for (int mt = 0; mt < 4; mt++)
#pragma unroll
                for (int nt = 0; nt < 8; nt++)
                    mma_f16(acc[mt][nt], a[mt], bf[nt][0], bf[nt][1]);
        }
    }

#pragma unroll
    for (int mt = 0; mt < 4; mt++) {
        int r0 = m0 + wm * 64 + mt * 16 + (lane >> 2);
#pragma unroll
        for (int nt = 0; nt < 8; nt++) {
            int c = n0 + wn * 64 + nt * 8 + (lane & 3) * 2;
            float* p0 = out + ((size_t)b * LQL + r0) * DDIM + c;
            *(float2*)p0              = make_float2(acc[mt][nt][0], acc[mt][nt][1]);
            *(float2*)(p0 + 8 * DDIM) = make_float2(acc[mt][nt][2], acc[mt][nt][3]);
        }
    }
}

// ---------------- launch ------------------------------------------------------
extern "C" void kernel_launch(void* const* d_in, const int* in_sizes, int n_in,
                              void* d_out, int out_size) {
    const float* q  = (const float*)d_in[0];
    const float* k  = (const float*)d_in[1];
    const float* v  = (const float*)d_in[2];
    const int*   kl = (const int*)d_in[3];
    float* out = (float*)d_out;

    cudaFuncSetAttribute(gemm_qk_kernel, cudaFuncAttributeMaxDynamicSharedMemorySize, QK_SMEM);
    cudaFuncSetAttribute(gemm_pv_kernel, cudaFuncAttributeMaxDynamicSharedMemorySize, PV_SMEM);

    const int n4 = BB * LQL * DDIM / 4;   // 8388608
    cvt_qk_kernel<<<n4 / 256, 256>>>((const float4*)q, (const float4*)k, n4);
    cvt_v_t_kernel<<<dim3(DDIM / 32, LKL / 64, BB), dim3(32, 8)>>>(v);

    gemm_qk_kernel<<<dim3(LKL / BN, LQL / BM, BB), 128, QK_SMEM>>>(kl);
    softmax_kernel<<<BB * LQL, 256>>>(kl);
    gemm_pv_kernel<<<dim3(DDIM / BN, LQL / BM, BB), 128, PV_SMEM>>>(out, kl);
}

// round 14
// speedup vs baseline: 1.9148x; 1.0440x over previous
#include <cuda_runtime.h>
#include <cuda_fp16.h>
#include <cstdint>
#include <cstddef>

#define BB   16
#define LQL  2048
#define LKL  2048
#define DDIM 1024

#define BM 128
#define BN 128
#define NS  3

// ---- QK staging: BK=32 halves (64B rows), 4 tiles per stage ----
#define QK_BK 32
#define QK_TILE_B  8192                      // 128 rows * 64 B
#define QK_STAGE_B (4 * QK_TILE_B)           // Qh,Ql,Kh,Kl
#define QK_SMEM    (NS * QK_STAGE_B)         // 98304 B -> 2 CTAs/SM

// ---- PV staging: BK=32, 2 tiles (P, Vt) per stage, 4 stages ----
#define PV_NS 4
#define PV_BK 32
#define PV_TILE_B 8192
#define PV_STAGE_B (2 * PV_TILE_B)           // 16 KB
#define PV_SMEM (PV_NS * PV_STAGE_B)         // 65536 B -> 2 CTAs/SM

// ---------------- scratch (static device globals; zero-initialized) ----------
__device__ __align__(16) __half g_Qh[(size_t)BB * LQL * DDIM];
__device__ __align__(16) __half g_Ql[(size_t)BB * LQL * DDIM];
__device__ __align__(16) __half g_Kh[(size_t)BB * LKL * DDIM];
__device__ __align__(16) __half g_Kl[(size_t)BB * LKL * DDIM];
__device__ __align__(16) __half g_Vt[(size_t)BB * DDIM * LKL];  // V^T: [b][d][k]
__device__ __align__(16) float  g_S [(size_t)BB * LQL * LKL];
__device__ __align__(16) __half g_P [(size_t)BB * LQL * LKL];

// ---------------- PTX helpers ------------------------------------------------
__device__ __forceinline__ uint32_t s2u(const void* p) {
    return (uint32_t)__cvta_generic_to_shared(p);
}
__device__ __forceinline__ uint32_t sw64(uint32_t o) { return o ^ ((o >> 3) & 0x30); }

__device__ __forceinline__ void ldm4(uint32_t* r, uint32_t a) {
    asm volatile("ldmatrix.sync.aligned.m8n8.x4.shared.b16 {%0,%1,%2,%3},[%4];"
                 : "=r"(r[0]), "=r"(r[1]), "=r"(r[2]), "=r"(r[3]) : "r"(a));
}
__device__ __forceinline__ void mma_f16(float* c, const uint32_t* a, uint32_t b0, uint32_t b1) {
    asm volatile("mma.sync.aligned.m16n8k16.row.col.f32.f16.f16.f32 "
                 "{%0,%1,%2,%3},{%4,%5,%6,%7},{%8,%9},{%0,%1,%2,%3};"
                 : "+f"(c[0]), "+f"(c[1]), "+f"(c[2]), "+f"(c[3])
                 : "r"(a[0]), "r"(a[1]), "r"(a[2]), "r"(a[3]), "r"(b0), "r"(b1));
}
__device__ __forceinline__ void cpa16(uint32_t s, const void* g) {
    asm volatile("cp.async.cg.shared.global [%0],[%1],16;" :: "r"(s), "l"(g));
}
__device__ __forceinline__ void cpcommit() { asm volatile("cp.async.commit_group;"); }

// ---------------- conversion: Q,K hi/lo split (K rows masked by key_len) ----
__global__ void cvt_qk_kernel(const float4* __restrict__ q,
                              const float4* __restrict__ k,
                              const int* __restrict__ key_len, int n4) {
    int i = blockIdx.x * blockDim.x + threadIdx.x;
    if (i >= n4) return;
    {
        float4 x = q[i];
        __half h0 = __float2half_rn(x.x), h1 = __float2half_rn(x.y);
        __half h2 = __float2half_rn(x.z), h3 = __float2half_rn(x.w);
        ((__half2*)g_Qh)[2 * i]     = __halves2half2(h0, h1);
        ((__half2*)g_Qh)[2 * i + 1] = __halves2half2(h2, h3);
        ((__half2*)g_Ql)[2 * i]     = __halves2half2(
            __float2half_rn(x.x - __half2float(h0)), __float2half_rn(x.y - __half2float(h1)));
        ((__half2*)g_Ql)[2 * i + 1] = __halves2half2(
            __float2half_rn(x.z - __half2float(h2)), __float2half_rn(x.w - __half2float(h3)));
    }
    {
        // K row within batch: per batch 2048 rows x 256 float4 chunks (2^19 chunks)
        int klb = __ldg(&key_len[i >> 19]);
        int row = (i & 524287) >> 8;
        int kmaxK = ((klb + 127) >> 7) << 7;   // QK reads K rows < ceil(kl/128)*128
        if (row < kmaxK) {
            float4 x = k[i];
            __half h0 = __float2half_rn(x.x), h1 = __float2half_rn(x.y);
            __half h2 = __float2half_rn(x.z), h3 = __float2half_rn(x.w);
            ((__half2*)g_Kh)[2 * i]     = __halves2half2(h0, h1);
            ((__half2*)g_Kh)[2 * i + 1] = __halves2half2(h2, h3);
            ((__half2*)g_Kl)[2 * i]     = __halves2half2(
                __float2half_rn(x.x - __half2float(h0)), __float2half_rn(x.y - __half2float(h1)));
            ((__half2*)g_Kl)[2 * i + 1] = __halves2half2(
                __float2half_rn(x.z - __half2float(h2)), __float2half_rn(x.w - __half2float(h3)));
        }
    }
}

// V [b][k][d] fp32 -> g_Vt [b][d][k] fp16; 64(k) x 32(d) tiles, half2 stores.
// Skips k-tiles beyond what PV reads (k < ceil(kl/32)*32; all when kl==0).
__global__ void cvt_v_t_kernel(const float* __restrict__ v,
                               const int* __restrict__ key_len) {
    int b  = blockIdx.z;
    int k0 = blockIdx.y * 64;
    int klb = __ldg(&key_len[b]);
    int kmax = (klb == 0) ? LKL : (((klb + 63) >> 6) << 6);
    if (k0 >= kmax) return;

    __shared__ __half tile[64][33];              // [k][d], pad
    int d0 = blockIdx.x * 32;
    int x = threadIdx.x, y = threadIdx.y;        // 32 x 8
    const float* src = v + ((size_t)b * LKL + k0) * DDIM + d0;
#pragma unroll
    for (int i = 0; i < 8; i++)                  // 64 k-rows
        tile[y + 8 * i][x] = __float2half_rn(src[(size_t)(y + 8 * i) * DDIM + x]);
    __syncthreads();
    __half* dst = g_Vt + ((size_t)b * DDIM + d0) * LKL + k0;
#pragma unroll
    for (int i = 0; i < 4; i++) {                // 32 d-rows, 64 k each as half2
        int d = y + 8 * i;
        __half2 hv = __halves2half2(tile[2 * x][d], tile[2 * x + 1][d]);
        *(__half2*)(dst + (size_t)d * LKL + 2 * x) = hv;
    }
}

// ---- GEMM1: S = Q K^T, fused 3-pass, 4 warps, warp tile 64x64 ---------------
__global__ __launch_bounds__(128, 2)
void gemm_qk_kernel(const int* __restrict__ key_len) {
    int b  = blockIdx.z;
    int kl = key_len[b];
    int n0 = blockIdx.x * BN;
    if (n0 >= kl) return;            // masked tile (also kl==0)
    int m0 = blockIdx.y * BM;

    extern __shared__ __half sm[];
    uint32_t smb = s2u(sm);

    int tid = threadIdx.x;
    const __half* srcQh = g_Qh + ((size_t)b * LQL + m0) * DDIM;
    const __half* srcQl = g_Ql + ((size_t)b * LQL + m0) * DDIM;
    const __half* srcKh = g_Kh + ((size_t)b * LKL + n0) * DDIM;
    const __half* srcKl = g_Kl + ((size_t)b * LKL + n0) * DDIM;

    int lc = tid & 3, lr = tid >> 2;

    auto issue = [&](int t) {
        int k0 = t * QK_BK;
        uint32_t st = smb + (t % NS) * QK_STAGE_B;
        const __half* pQh = srcQh + k0 + lc * 8;
        const __half* pQl = srcQl + k0 + lc * 8;
        const __half* pKh = srcKh + k0 + lc * 8;
        const __half* pKl = srcKl + k0 + lc * 8;
#pragma unroll
        for (int p = 0; p < 4; p++) {
            int row = p * 32 + lr;
            uint32_t so = sw64(row * 64 + lc * 16);
            cpa16(st + so,                 pQh + (size_t)row * DDIM);
            cpa16(st + QK_TILE_B + so,     pQl + (size_t)row * DDIM);
            cpa16(st + 2 * QK_TILE_B + so, pKh + (size_t)row * DDIM);
            cpa16(st + 3 * QK_TILE_B + so, pKl + (size_t)row * DDIM);
        }
        cpcommit();
    };

    float acc[4][8][4];
#pragma unroll
    for (int mt = 0; mt < 4; mt++)
#pragma unroll
        for (int nt = 0; nt < 8; nt++)
#pragma unroll
            for (int j = 0; j < 4; j++) acc[mt][nt][j] = 0.0f;

    int lane = tid & 31, wid = tid >> 5;
    int wm = wid >> 1, wn = wid & 1;              // 2x2 grid, warp tile 64x64
    int arow = lane & 15, ac = lane >> 4;
    int g    = lane >> 3;
    int brow = (lane & 7) + ((g >> 1) << 3);
    int bc   = g & 1;

    const int KT = DDIM / QK_BK;                  // 32
    issue(0);
    issue(1);

    for (int s = 0; s < KT; s++) {
        if (s + 1 < KT) asm volatile("cp.async.wait_group 1;");
        else            asm volatile("cp.async.wait_group 0;");
        __syncthreads();
        if (s + 2 < KT) issue(s + 2);

        uint32_t st = smb + (s % NS) * QK_STAGE_B;
        uint32_t tQh = st, tQl = st + QK_TILE_B;
        uint32_t tKh = st + 2 * QK_TILE_B, tKl = st + 3 * QK_TILE_B;

#pragma unroll
        for (int kk = 0; kk < 2; kk++) {
            uint32_t aQh[4][4], aQl[4][4], bh[8][2], bl[8][2];
#pragma unroll
            for (int nt2 = 0; nt2 < 4; nt2++) {
                uint32_t off = sw64((wn * 64 + nt2 * 16 + brow) * 64 + (kk * 2 + bc) * 16);
                uint32_t r[4];
                ldm4(r, tKh + off);
                bh[nt2 * 2][0] = r[0];     bh[nt2 * 2][1] = r[1];
                bh[nt2 * 2 + 1][0] = r[2]; bh[nt2 * 2 + 1][1] = r[3];
                ldm4(r, tKl + off);
                bl[nt2 * 2][0] = r[0];     bl[nt2 * 2][1] = r[1];
                bl[nt2 * 2 + 1][0] = r[2]; bl[nt2 * 2 + 1][1] = r[3];
            }
#pragma unroll
            for (int mt = 0; mt < 4; mt++) {
                uint32_t off = sw64((wm * 64 + mt * 16 + arow) * 64 + (kk * 2 + ac) * 16);
                ldm4(aQh[mt], tQh + off);
            }
#pragma unroll
            for (int mt = 0; mt < 4; mt++) {
                uint32_t off = sw64((wm * 64 + mt * 16 + arow) * 64 + (kk * 2 + ac) * 16);
                ldm4(aQl[mt], tQl + off);
            }
#pragma unroll
            for (int mt = 0; mt < 4; mt++)
#pragma unroll
                for (int nt = 0; nt < 8; nt++)
                    mma_f16(acc[mt][nt], aQh[mt], bh[nt][0], bh[nt][1]);
#pragma unroll
            for (int mt = 0; mt < 4; mt++)
#pragma unroll
                for (int nt = 0; nt < 8; nt++)
                    mma_f16(acc[mt][nt], aQh[mt], bl[nt][0], bl[nt][1]);
#pragma unroll
            for (int mt = 0; mt < 4; mt++)
#pragma unroll
                for (int nt = 0; nt < 8; nt++)
                    mma_f16(acc[mt][nt], aQl[mt], bh[nt][0], bh[nt][1]);
        }
    }

#pragma unroll
    for (int mt = 0; mt < 4; mt++) {
        int r0 = m0 + wm * 64 + mt * 16 + (lane >> 2);
#pragma unroll
        for (int nt = 0; nt < 8; nt++) {
            int c = n0 + wn * 64 + nt * 8 + (lane & 3) * 2;
            float* p0 = g_S + ((size_t)b * LQL + r0) * LKL + c;
            *(float2*)p0             = make_float2(acc[mt][nt][0], acc[mt][nt][1]);
            *(float2*)(p0 + 8 * LKL) = make_float2(acc[mt][nt][2], acc[mt][nt][3]);
        }
    }
}

// ---------------- row softmax: masked loads, register-resident ---------------
__global__ __launch_bounds__(256)
void softmax_kernel(const int* __restrict__ key_len) {
    int row = blockIdx.x;
    int b = row >> 11;
    int kl = key_len[b];
    __half* prow = g_P + (size_t)row * LKL;
    int tid = threadIdx.x;
    int lane = tid & 31, wid = tid >> 5;

    if (kl == 0) {                   // all masked -> uniform softmax
        __half2 u2 = __halves2half2(__float2half(1.0f / 2048.0f), __float2half(1.0f / 2048.0f));
        __half2* p2 = (__half2*)prow;
        for (int i = tid; i < LKL / 2; i += 256) p2[i] = u2;
        return;
    }

    const float4* s4 = (const float4*)(g_S + (size_t)row * LKL);
    __shared__ float red[8];

    float4 v[2];
    float lmax = -3.4e38f;
#pragma unroll
    for (int j = 0; j < 2; j++) {
        int idx = j * 256 + tid;
        int k0 = idx << 2;
        if (k0 < kl) {
            v[j] = s4[idx];
            if (k0 + 1 >= kl) v[j].y = -3.4e38f;
            if (k0 + 2 >= kl) v[j].z = -3.4e38f;
            if (k0 + 3 >= kl) v[j].w = -3.4e38f;
            lmax = fmaxf(fmaxf(lmax, fmaxf(v[j].x, v[j].y)), fmaxf(v[j].z, v[j].w));
        } else {
            v[j] = make_float4(-3.4e38f, -3.4e38f, -3.4e38f, -3.4e38f);
        }
    }
#pragma unroll
    for (int o = 16; o > 0; o >>= 1)
        lmax = fmaxf(lmax, __shfl_xor_sync(0xffffffffu, lmax, o));
    if (lane == 0) red[wid] = lmax;
    __syncthreads();
    float m = fmaxf(fmaxf(fmaxf(red[0], red[1]), fmaxf(red[2], red[3])),
                    fmaxf(fmaxf(red[4], red[5]), fmaxf(red[6], red[7])));
    __syncthreads();

    float lsum = 0.0f;
#pragma unroll
    for (int j = 0; j < 2; j++) {
        v[j].x = __expf(v[j].x - m);
        v[j].y = __expf(v[j].y - m);
        v[j].z = __expf(v[j].z - m);
        v[j].w = __expf(v[j].w - m);
        lsum += (v[j].x + v[j].y) + (v[j].z + v[j].w);
    }
#pragma unroll
    for (int o = 16; o > 0; o >>= 1)
        lsum += __shfl_xor_sync(0xffffffffu, lsum, o);
    if (lane == 0) red[wid] = lsum;
    __syncthreads();
    float inv = 1.0f / (red[0] + red[1] + red[2] + red[3] +
                        red[4] + red[5] + red[6] + red[7]);

    int kmax = ((kl + 63) >> 6) << 6;
#pragma unroll
    for (int j = 0; j < 2; j++) {
        int idx = j * 256 + tid;
        int k0 = idx << 2;
        if (k0 < kmax) {
            __half2 h0 = __halves2half2(__float2half(v[j].x * inv), __float2half(v[j].y * inv));
            __half2 h1 = __halves2half2(__float2half(v[j].z * inv), __float2half(v[j].w * inv));
            uint2 pack;
            pack.x = *(uint32_t*)&h0;
            pack.y = *(uint32_t*)&h1;
            *(uint2*)(prow + k0) = pack;
        }
    }
}

// ---- GEMM2: O = P V  (BK=32, normal ldm4 both operands, NS=4) ---------------
__global__ __launch_bounds__(128, 2)
void gemm_pv_kernel(float* __restrict__ out, const int* __restrict__ key_len) {
    int b  = blockIdx.z;
    int kl = key_len[b];
    int n0 = blockIdx.x * BN;        // over D
    int m0 = blockIdx.y * BM;

    extern __shared__ __half sm[];
    uint32_t smb = s2u(sm);
    int tid = threadIdx.x;

    const __half* srcP  = g_P  + ((size_t)b * LQL + m0) * LKL;
    const __half* srcVt = g_Vt + ((size_t)b * DDIM + n0) * LKL;

    int lc = tid & 3, lr = tid >> 2;

    auto issue = [&](int t) {
        int k0 = t * PV_BK;
        uint32_t st = smb + (t % PV_NS) * PV_STAGE_B;
        const __half* pP = srcP  + k0 + lc * 8;
        const __half* pV = srcVt + k0 + lc * 8;
#pragma unroll
        for (int p = 0; p < 4; p++) {
            int row = p * 32 + lr;
            uint32_t so = sw64(row * 64 + lc * 16);
            cpa16(st + so,             pP + (size_t)row * LKL);
            cpa16(st + PV_TILE_B + so, pV + (size_t)row * LKL);
        }
        cpcommit();
    };

    float acc[4][8][4];
#pragma unroll
    for (int mt = 0; mt < 4; mt++)
#pragma unroll
        for (int nt = 0; nt < 8; nt++)
#pragma unroll
            for (int j = 0; j < 4; j++) acc[mt][nt][j] = 0.0f;

    int lane = tid & 31, wid = tid >> 5;
    int wm = wid >> 1, wn = wid & 1;              // 2x2 grid, warp tile 64x64
    int arow = lane & 15, ac = lane >> 4;
    int g    = lane >> 3;
    int brow = (lane & 7) + ((g >> 1) << 3);
    int bc   = g & 1;

    int KT = (kl == 0) ? (LKL / PV_BK) : ((kl + PV_BK - 1) >> 5);

    issue(0);
    if (KT > 1) issue(1);
    if (KT > 2) issue(2);

    for (int s = 0; s < KT; s++) {
        if (s + 1 < KT) {
            if (s + 2 < KT) asm volatile("cp.async.wait_group 2;");
            else            asm volatile("cp.async.wait_group 1;");
        } else              asm volatile("cp.async.wait_group 0;");
        __syncthreads();
        if (s + 3 < KT) issue(s + 3);

        uint32_t st = smb + (s % PV_NS) * PV_STAGE_B;
        uint32_t tP = st, tV = st + PV_TILE_B;

#pragma unroll
        for (int kk = 0; kk < 2; kk++) {
            uint32_t a[4][4], bf[8][2];
#pragma unroll
            for (int nt2 = 0; nt2 < 4; nt2++) {
                uint32_t off = sw64((wn * 64 + nt2 * 16 + brow) * 64 + (kk * 2 + bc) * 16);
                uint32_t r[4];
                ldm4(r, tV + off);
                bf[nt2 * 2][0] = r[0];     bf[nt2 * 2][1] = r[1];
                bf[nt2 * 2 + 1][0] = r[2]; bf[nt2 * 2 + 1][1] = r[3];
            }
#pragma unroll
            for (int mt = 0; mt < 4; mt++) {
                uint32_t off = sw64((wm * 64 + mt * 16 + arow) * 64 + (kk * 2 + ac) * 16);
                ldm4(a[mt], tP + off);
            }
#pragma unroll
            for (int mt = 0; mt < 4; mt++)
#pragma unroll
                for (int nt = 0; nt < 8; nt++)
                    mma_f16(acc[mt][nt], a[mt], bf[nt][0], bf[nt][1]);
        }
    }

#pragma unroll
    for (int mt = 0; mt < 4; mt++) {
        int r0 = m0 + wm * 64 + mt * 16 + (lane >> 2);
#pragma unroll
        for (int nt = 0; nt < 8; nt++) {
            int c = n0 + wn * 64 + nt * 8 + (lane & 3) * 2;
            float* p0 = out + ((size_t)b * LQL + r0) * DDIM + c;
            *(float2*)p0              = make_float2(acc[mt][nt][0], acc[mt][nt][1]);
            *(float2*)(p0 + 8 * DDIM) = make_float2(acc[mt][nt][2], acc[mt][nt][3]);
        }
    }
}

// ---------------- launch ------------------------------------------------------
extern "C" void kernel_launch(void* const* d_in, const int* in_sizes, int n_in,
                              void* d_out, int out_size) {
    const float* q  = (const float*)d_in[0];
    const float* k  = (const float*)d_in[1];
    const float* v  = (const float*)d_in[2];
    const int*   kl = (const int*)d_in[3];
    float* out = (float*)d_out;

    cudaFuncSetAttribute(gemm_qk_kernel, cudaFuncAttributeMaxDynamicSharedMemorySize, QK_SMEM);
    cudaFuncSetAttribute(gemm_pv_kernel, cudaFuncAttributeMaxDynamicSharedMemorySize, PV_SMEM);

    const int n4 = BB * LQL * DDIM / 4;   // 8388608
    cvt_qk_kernel<<<n4 / 256, 256>>>((const float4*)q, (const float4*)k, kl, n4);
    cvt_v_t_kernel<<<dim3(DDIM / 32, LKL / 64, BB), dim3(32, 8)>>>(v, kl);

    gemm_qk_kernel<<<dim3(LKL / BN, LQL / BM, BB), 128, QK_SMEM>>>(kl);
    softmax_kernel<<<BB * LQL, 256>>>(kl);
    gemm_pv_kernel<<<dim3(DDIM / BN, LQL / BM, BB), 128, PV_SMEM>>>(out, kl);
}

// round 15
// speedup vs baseline: 1.9581x; 1.0226x over previous
#include <cuda_runtime.h>
#include <cuda_fp16.h>
#include <cstdint>
#include <cstddef>

#define BB   16
#define LQL  2048
#define LKL  2048
#define DDIM 1024

#define BM 128
#define BN 128
#define NS  3

// ---- QK staging: BK=32 halves (64B rows), 4 tiles per stage ----
#define QK_BK 32
#define QK_TILE_B  8192                      // 128 rows * 64 B
#define QK_STAGE_B (4 * QK_TILE_B)           // Qh,Ql,Kh,Kl
#define QK_SMEM    (NS * QK_STAGE_B)         // 98304 B -> 2 CTAs/SM

// ---- PV staging: BK=32, 2 tiles (P, Vt) per stage, 4 stages ----
#define PV_NS 4
#define PV_BK 32
#define PV_TILE_B 8192
#define PV_STAGE_B (2 * PV_TILE_B)           // 16 KB
#define PV_SMEM (PV_NS * PV_STAGE_B)         // 65536 B -> 2 CTAs/SM

// conversion kernel block split
#define CVT_QK_BLOCKS 32768                  // n4 / 256
#define CVT_V_BLOCKS  (16 * 32 * 32)         // b * ktiles(64) * dtiles(32)

// ---------------- scratch (static device globals; zero-initialized) ----------
__device__ __align__(16) __half g_Qh[(size_t)BB * LQL * DDIM];
__device__ __align__(16) __half g_Ql[(size_t)BB * LQL * DDIM];
__device__ __align__(16) __half g_Kh[(size_t)BB * LKL * DDIM];
__device__ __align__(16) __half g_Kl[(size_t)BB * LKL * DDIM];
__device__ __align__(16) __half g_Vt[(size_t)BB * DDIM * LKL];  // V^T: [b][d][k]
__device__ __align__(16) float  g_S [(size_t)BB * LQL * LKL];
__device__ __align__(16) __half g_P [(size_t)BB * LQL * LKL];

// ---------------- PTX helpers ------------------------------------------------
__device__ __forceinline__ uint32_t s2u(const void* p) {
    return (uint32_t)__cvta_generic_to_shared(p);
}
__device__ __forceinline__ uint32_t sw64(uint32_t o) { return o ^ ((o >> 3) & 0x30); }

__device__ __forceinline__ void ldm4(uint32_t* r, uint32_t a) {
    asm volatile("ldmatrix.sync.aligned.m8n8.x4.shared.b16 {%0,%1,%2,%3},[%4];"
                 : "=r"(r[0]), "=r"(r[1]), "=r"(r[2]), "=r"(r[3]) : "r"(a));
}
__device__ __forceinline__ void mma_f16(float* c, const uint32_t* a, uint32_t b0, uint32_t b1) {
    asm volatile("mma.sync.aligned.m16n8k16.row.col.f32.f16.f16.f32 "
                 "{%0,%1,%2,%3},{%4,%5,%6,%7},{%8,%9},{%0,%1,%2,%3};"
                 : "+f"(c[0]), "+f"(c[1]), "+f"(c[2]), "+f"(c[3])
                 : "r"(a[0]), "r"(a[1]), "r"(a[2]), "r"(a[3]), "r"(b0), "r"(b1));
}
__device__ __forceinline__ void cpa16(uint32_t s, const void* g) {
    asm volatile("cp.async.cg.shared.global [%0],[%1],16;" :: "r"(s), "l"(g));
}
__device__ __forceinline__ void cpcommit() { asm volatile("cp.async.commit_group;"); }

// ---------------- merged conversion kernel -----------------------------------
// blocks [0, CVT_QK_BLOCKS): Q,K hi/lo split (K rows masked by key_len)
// blocks [CVT_QK_BLOCKS, +CVT_V_BLOCKS): V transpose (masked by key_len)
__global__ __launch_bounds__(256)
void cvt_all_kernel(const float4* __restrict__ q,
                    const float4* __restrict__ k,
                    const float* __restrict__ v,
                    const int* __restrict__ key_len) {
    __shared__ __half tile[64][33];
    int bx = blockIdx.x;

    if (bx < CVT_QK_BLOCKS) {
        int i = bx * 256 + threadIdx.x;
        {
            float4 x = q[i];
            __half h0 = __float2half_rn(x.x), h1 = __float2half_rn(x.y);
            __half h2 = __float2half_rn(x.z), h3 = __float2half_rn(x.w);
            ((__half2*)g_Qh)[2 * i]     = __halves2half2(h0, h1);
            ((__half2*)g_Qh)[2 * i + 1] = __halves2half2(h2, h3);
            ((__half2*)g_Ql)[2 * i]     = __halves2half2(
                __float2half_rn(x.x - __half2float(h0)), __float2half_rn(x.y - __half2float(h1)));
            ((__half2*)g_Ql)[2 * i + 1] = __halves2half2(
                __float2half_rn(x.z - __half2float(h2)), __float2half_rn(x.w - __half2float(h3)));
        }
        {
            int klb = __ldg(&key_len[i >> 19]);
            int row = (i & 524287) >> 8;
            int kmaxK = ((klb + 127) >> 7) << 7;   // QK reads K rows < ceil(kl/128)*128
            if (row < kmaxK) {
                float4 x = k[i];
                __half h0 = __float2half_rn(x.x), h1 = __float2half_rn(x.y);
                __half h2 = __float2half_rn(x.z), h3 = __float2half_rn(x.w);
                ((__half2*)g_Kh)[2 * i]     = __halves2half2(h0, h1);
                ((__half2*)g_Kh)[2 * i + 1] = __halves2half2(h2, h3);
                ((__half2*)g_Kl)[2 * i]     = __halves2half2(
                    __float2half_rn(x.x - __half2float(h0)), __float2half_rn(x.y - __half2float(h1)));
                ((__half2*)g_Kl)[2 * i + 1] = __halves2half2(
                    __float2half_rn(x.z - __half2float(h2)), __float2half_rn(x.w - __half2float(h3)));
            }
        }
    } else {
        int id = bx - CVT_QK_BLOCKS;
        int b  = id >> 10;
        int rem = id & 1023;
        int k0 = (rem >> 5) * 64;
        int d0 = (rem & 31) * 32;
        int klb = __ldg(&key_len[b]);
        int kmax = (klb == 0) ? LKL : (((klb + 63) >> 6) << 6);
        if (k0 >= kmax) return;

        int x = threadIdx.x & 31, y = threadIdx.x >> 5;   // 32 x 8
        const float* src = v + ((size_t)b * LKL + k0) * DDIM + d0;
#pragma unroll
        for (int i = 0; i < 8; i++)                       // 64 k-rows
            tile[y + 8 * i][x] = __float2half_rn(src[(size_t)(y + 8 * i) * DDIM + x]);
        __syncthreads();
        __half* dst = g_Vt + ((size_t)b * DDIM + d0) * LKL + k0;
#pragma unroll
        for (int i = 0; i < 4; i++) {                     // 32 d-rows, half2 stores
            int d = y + 8 * i;
            __half2 hv = __halves2half2(tile[2 * x][d], tile[2 * x + 1][d]);
            *(__half2*)(dst + (size_t)d * LKL + 2 * x) = hv;
        }
    }
}

// ---- GEMM1: S = Q K^T, fused 3-pass, 4 warps, warp tile 64x64 ---------------
__global__ __launch_bounds__(128, 2)
void gemm_qk_kernel(const int* __restrict__ key_len) {
    int b  = blockIdx.z;
    int kl = key_len[b];
    int n0 = blockIdx.x * BN;
    if (n0 >= kl) return;            // masked tile (also kl==0)
    int m0 = blockIdx.y * BM;

    extern __shared__ __half sm[];
    uint32_t smb = s2u(sm);

    int tid = threadIdx.x;
    const __half* srcQh = g_Qh + ((size_t)b * LQL + m0) * DDIM;
    const __half* srcQl = g_Ql + ((size_t)b * LQL + m0) * DDIM;
    const __half* srcKh = g_Kh + ((size_t)b * LKL + n0) * DDIM;
    const __half* srcKl = g_Kl + ((size_t)b * LKL + n0) * DDIM;

    int lc = tid & 3, lr = tid >> 2;

    auto issue = [&](int t) {
        int k0 = t * QK_BK;
        uint32_t st = smb + (t % NS) * QK_STAGE_B;
        const __half* pQh = srcQh + k0 + lc * 8;
        const __half* pQl = srcQl + k0 + lc * 8;
        const __half* pKh = srcKh + k0 + lc * 8;
        const __half* pKl = srcKl + k0 + lc * 8;
#pragma unroll
        for (int p = 0; p < 4; p++) {
            int row = p * 32 + lr;
            uint32_t so = sw64(row * 64 + lc * 16);
            cpa16(st + so,                 pQh + (size_t)row * DDIM);
            cpa16(st + QK_TILE_B + so,     pQl + (size_t)row * DDIM);
            cpa16(st + 2 * QK_TILE_B + so, pKh + (size_t)row * DDIM);
            cpa16(st + 3 * QK_TILE_B + so, pKl + (size_t)row * DDIM);
        }
        cpcommit();
    };

    float acc[4][8][4];
#pragma unroll
    for (int mt = 0; mt < 4; mt++)
#pragma unroll
        for (int nt = 0; nt < 8; nt++)
#pragma unroll
            for (int j = 0; j < 4; j++) acc[mt][nt][j] = 0.0f;

    int lane = tid & 31, wid = tid >> 5;
    int wm = wid >> 1, wn = wid & 1;              // 2x2 grid, warp tile 64x64
    int arow = lane & 15, ac = lane >> 4;
    int g    = lane >> 3;
    int brow = (lane & 7) + ((g >> 1) << 3);
    int bc   = g & 1;

    const int KT = DDIM / QK_BK;                  // 32
    issue(0);
    issue(1);

    for (int s = 0; s < KT; s++) {
        if (s + 1 < KT) asm volatile("cp.async.wait_group 1;");
        else            asm volatile("cp.async.wait_group 0;");
        __syncthreads();
        if (s + 2 < KT) issue(s + 2);

        uint32_t st = smb + (s % NS) * QK_STAGE_B;
        uint32_t tQh = st, tQl = st + QK_TILE_B;
        uint32_t tKh = st + 2 * QK_TILE_B, tKl = st + 3 * QK_TILE_B;

#pragma unroll
        for (int kk = 0; kk < 2; kk++) {
            uint32_t aQh[4][4], aQl[4][4], bh[8][2], bl[8][2];
#pragma unroll
            for (int nt2 = 0; nt2 < 4; nt2++) {
                uint32_t off = sw64((wn * 64 + nt2 * 16 + brow) * 64 + (kk * 2 + bc) * 16);
                uint32_t r[4];
                ldm4(r, tKh + off);
                bh[nt2 * 2][0] = r[0];     bh[nt2 * 2][1] = r[1];
                bh[nt2 * 2 + 1][0] = r[2]; bh[nt2 * 2 + 1][1] = r[3];
                ldm4(r, tKl + off);
                bl[nt2 * 2][0] = r[0];     bl[nt2 * 2][1] = r[1];
                bl[nt2 * 2 + 1][0] = r[2]; bl[nt2 * 2 + 1][1] = r[3];
            }
#pragma unroll
            for (int mt = 0; mt < 4; mt++) {
                uint32_t off = sw64((wm * 64 + mt * 16 + arow) * 64 + (kk * 2 + ac) * 16);
                ldm4(aQh[mt], tQh + off);
            }
#pragma unroll
            for (int mt = 0; mt < 4; mt++) {
                uint32_t off = sw64((wm * 64 + mt * 16 + arow) * 64 + (kk * 2 + ac) * 16);
                ldm4(aQl[mt], tQl + off);
            }
#pragma unroll
            for (int mt = 0; mt < 4; mt++)
#pragma unroll
                for (int nt = 0; nt < 8; nt++)
                    mma_f16(acc[mt][nt], aQh[mt], bh[nt][0], bh[nt][1]);
#pragma unroll
            for (int mt = 0; mt < 4; mt++)
#pragma unroll
                for (int nt = 0; nt < 8; nt++)
                    mma_f16(acc[mt][nt], aQh[mt], bl[nt][0], bl[nt][1]);
#pragma unroll
            for (int mt = 0; mt < 4; mt++)
#pragma unroll
                for (int nt = 0; nt < 8; nt++)
                    mma_f16(acc[mt][nt], aQl[mt], bh[nt][0], bh[nt][1]);
        }
    }

#pragma unroll
    for (int mt = 0; mt < 4; mt++) {
        int r0 = m0 + wm * 64 + mt * 16 + (lane >> 2);
#pragma unroll
        for (int nt = 0; nt < 8; nt++) {
            int c = n0 + wn * 64 + nt * 8 + (lane & 3) * 2;
            float* p0 = g_S + ((size_t)b * LQL + r0) * LKL + c;
            *(float2*)p0             = make_float2(acc[mt][nt][0], acc[mt][nt][1]);
            *(float2*)(p0 + 8 * LKL) = make_float2(acc[mt][nt][2], acc[mt][nt][3]);
        }
    }
}

// ---------------- row softmax: 128 threads, MLP=4, register-resident ---------
__global__ __launch_bounds__(128)
void softmax_kernel(const int* __restrict__ key_len) {
    int row = blockIdx.x;
    int b = row >> 11;
    int kl = key_len[b];
    __half* prow = g_P + (size_t)row * LKL;
    int tid = threadIdx.x;
    int lane = tid & 31, wid = tid >> 5;

    if (kl == 0) {                   // all masked -> uniform softmax
        __half2 u2 = __halves2half2(__float2half(1.0f / 2048.0f), __float2half(1.0f / 2048.0f));
        __half2* p2 = (__half2*)prow;
        for (int i = tid; i < LKL / 2; i += 128) p2[i] = u2;
        return;
    }

    const float4* s4 = (const float4*)(g_S + (size_t)row * LKL);
    __shared__ float red[4];

    // pass 1: 4 independent masked float4 loads per thread (MLP=4), block max
    float4 v[4];
    float lmax = -3.4e38f;
#pragma unroll
    for (int j = 0; j < 4; j++) {
        int idx = j * 128 + tid;
        int k0 = idx << 2;
        if (k0 < kl) {
            v[j] = s4[idx];
            if (k0 + 1 >= kl) v[j].y = -3.4e38f;
            if (k0 + 2 >= kl) v[j].z = -3.4e38f;
            if (k0 + 3 >= kl) v[j].w = -3.4e38f;
        } else {
            v[j] = make_float4(-3.4e38f, -3.4e38f, -3.4e38f, -3.4e38f);
        }
    }
#pragma unroll
    for (int j = 0; j < 4; j++)
        lmax = fmaxf(fmaxf(lmax, fmaxf(v[j].x, v[j].y)), fmaxf(v[j].z, v[j].w));
#pragma unroll
    for (int o = 16; o > 0; o >>= 1)
        lmax = fmaxf(lmax, __shfl_xor_sync(0xffffffffu, lmax, o));
    if (lane == 0) red[wid] = lmax;
    __syncthreads();
    float m = fmaxf(fmaxf(red[0], red[1]), fmaxf(red[2], red[3]));
    __syncthreads();

    // pass 2: exp + block sum
    float lsum = 0.0f;
#pragma unroll
    for (int j = 0; j < 4; j++) {
        v[j].x = __expf(v[j].x - m);
        v[j].y = __expf(v[j].y - m);
        v[j].z = __expf(v[j].z - m);
        v[j].w = __expf(v[j].w - m);
        lsum += (v[j].x + v[j].y) + (v[j].z + v[j].w);
    }
#pragma unroll
    for (int o = 16; o > 0; o >>= 1)
        lsum += __shfl_xor_sync(0xffffffffu, lsum, o);
    if (lane == 0) red[wid] = lsum;
    __syncthreads();
    float inv = 1.0f / (red[0] + red[1] + red[2] + red[3]);

    // pass 3: store fp16 up to ceil(kl/64)*64 (PV reads no further)
    int kmax = ((kl + 63) >> 6) << 6;
#pragma unroll
    for (int j = 0; j < 4; j++) {
        int idx = j * 128 + tid;
        int k0 = idx << 2;
        if (k0 < kmax) {
            __half2 h0 = __halves2half2(__float2half(v[j].x * inv), __float2half(v[j].y * inv));
            __half2 h1 = __halves2half2(__float2half(v[j].z * inv), __float2half(v[j].w * inv));
            uint2 pack;
            pack.x = *(uint32_t*)&h0;
            pack.y = *(uint32_t*)&h1;
            *(uint2*)(prow + k0) = pack;
        }
    }
}

// ---- GEMM2: O = P V  (BK=32, normal ldm4 both operands, NS=4) ---------------
__global__ __launch_bounds__(128, 2)
void gemm_pv_kernel(float* __restrict__ out, const int* __restrict__ key_len) {
    int b  = blockIdx.z;
    int kl = key_len[b];
    int n0 = blockIdx.x * BN;        // over D
    int m0 = blockIdx.y * BM;

    extern __shared__ __half sm[];
    uint32_t smb = s2u(sm);
    int tid = threadIdx.x;

    const __half* srcP  = g_P  + ((size_t)b * LQL + m0) * LKL;
    const __half* srcVt = g_Vt + ((size_t)b * DDIM + n0) * LKL;

    int lc = tid & 3, lr = tid >> 2;

    auto issue = [&](int t) {
        int k0 = t * PV_BK;
        uint32_t st = smb + (t % PV_NS) * PV_STAGE_B;
        const __half* pP = srcP  + k0 + lc * 8;
        const __half* pV = srcVt + k0 + lc * 8;
#pragma unroll
        for (int p = 0; p < 4; p++) {
            int row = p * 32 + lr;
            uint32_t so = sw64(row * 64 + lc * 16);
            cpa16(st + so,             pP + (size_t)row * LKL);
            cpa16(st + PV_TILE_B + so, pV + (size_t)row * LKL);
        }
        cpcommit();
    };

    float acc[4][8][4];
#pragma unroll
    for (int mt = 0; mt < 4; mt++)
#pragma unroll
        for (int nt = 0; nt < 8; nt++)
#pragma unroll
            for (int j = 0; j < 4; j++) acc[mt][nt][j] = 0.0f;

    int lane = tid & 31, wid = tid >> 5;
    int wm = wid >> 1, wn = wid & 1;              // 2x2 grid, warp tile 64x64
    int arow = lane & 15, ac = lane >> 4;
    int g    = lane >> 3;
    int brow = (lane & 7) + ((g >> 1) << 3);
    int bc   = g & 1;

    int KT = (kl == 0) ? (LKL / PV_BK) : ((kl + PV_BK - 1) >> 5);

    issue(0);
    if (KT > 1) issue(1);
    if (KT > 2) issue(2);

    for (int s = 0; s < KT; s++) {
        if (s + 1 < KT) {
            if (s + 2 < KT) asm volatile("cp.async.wait_group 2;");
            else            asm volatile("cp.async.wait_group 1;");
        } else              asm volatile("cp.async.wait_group 0;");
        __syncthreads();
        if (s + 3 < KT) issue(s + 3);

        uint32_t st = smb + (s % PV_NS) * PV_STAGE_B;
        uint32_t tP = st, tV = st + PV_TILE_B;

#pragma unroll
        for (int kk = 0; kk < 2; kk++) {
            uint32_t a[4][4], bf[8][2];
#pragma unroll
            for (int nt2 = 0; nt2 < 4; nt2++) {
                uint32_t off = sw64((wn * 64 + nt2 * 16 + brow) * 64 + (kk * 2 + bc) * 16);
                uint32_t r[4];
                ldm4(r, tV + off);
                bf[nt2 * 2][0] = r[0];     bf[nt2 * 2][1] = r[1];
                bf[nt2 * 2 + 1][0] = r[2]; bf[nt2 * 2 + 1][1] = r[3];
            }
#pragma unroll
            for (int mt = 0; mt < 4; mt++) {
                uint32_t off = sw64((wm * 64 + mt * 16 + arow) * 64 + (kk * 2 + ac) * 16);
                ldm4(a[mt], tP + off);
            }
#pragma unroll
            for (int mt = 0; mt < 4; mt++)
#pragma unroll
                for (int nt = 0; nt < 8; nt++)
                    mma_f16(acc[mt][nt], a[mt], bf[nt][0], bf[nt][1]);
        }
    }

#pragma unroll
    for (int mt = 0; mt < 4; mt++) {
        int r0 = m0 + wm * 64 + mt * 16 + (lane >> 2);
#pragma unroll
        for (int nt = 0; nt < 8; nt++) {
            int c = n0 + wn * 64 + nt * 8 + (lane & 3) * 2;
            float* p0 = out + ((size_t)b * LQL + r0) * DDIM + c;
            *(float2*)p0              = make_float2(acc[mt][nt][0], acc[mt][nt][1]);
            *(float2*)(p0 + 8 * DDIM) = make_float2(acc[mt][nt][2], acc[mt][nt][3]);
        }
    }
}

// ---------------- launch ------------------------------------------------------
extern "C" void kernel_launch(void* const* d_in, const int* in_sizes, int n_in,
                              void* d_out, int out_size) {
    const float* q  = (const float*)d_in[0];
    const float* k  = (const float*)d_in[1];
    const float* v  = (const float*)d_in[2];
    const int*   kl = (const int*)d_in[3];
    float* out = (float*)d_out;

    cudaFuncSetAttribute(gemm_qk_kernel, cudaFuncAttributeMaxDynamicSharedMemorySize, QK_SMEM);
    cudaFuncSetAttribute(gemm_pv_kernel, cudaFuncAttributeMaxDynamicSharedMemorySize, PV_SMEM);

    cvt_all_kernel<<<CVT_QK_BLOCKS + CVT_V_BLOCKS, 256>>>(
        (const float4*)q, (const float4*)k, v, kl);

    gemm_qk_kernel<<<dim3(LKL / BN, LQL / BM, BB), 128, QK_SMEM>>>(kl);
    softmax_kernel<<<BB * LQL, 128>>>(kl);
    gemm_pv_kernel<<<dim3(DDIM / BN, LQL / BM, BB), 128, PV_SMEM>>>(out, kl);
}